// round 11
// baseline (speedup 1.0000x reference)
#include <cuda_runtime.h>
#include <cuda_bf16.h>
#include <cstdint>
#include <math.h>

// ---------------------------------------------------------------------------
// Problem constants
// ---------------------------------------------------------------------------
#define VEG 4
#define WEA 8
#define HID 512
#define NB  256
#define T_HIST 150
#define T_FUT  50
#define HB (NB * HID)
#define XPW 64            // padded x width (12 real + 52 zeros)
#define GROW 2048         // gate rows (4*HID)
#define NTHREADS 256      // 8 warps per CTA, occupancy 2

// ---------------------------------------------------------------------------
// Device scratch (static only)
// ---------------------------------------------------------------------------
__device__ __nv_bfloat16 g_xph[T_HIST * NB * XPW];
__device__ __nv_bfloat16 g_xpl[T_HIST * NB * XPW];
__device__ __nv_bfloat16 g_xdh[NB * XPW];
__device__ __nv_bfloat16 g_xdl[NB * XPW];
__device__ float g_pred[NB * VEG];
__device__ __nv_bfloat16 g_y0h[T_HIST * HB];   // layer0 outputs hi (h-chain)
__device__ __nv_bfloat16 g_y0l[T_HIST * HB];
__device__ __nv_bfloat16 g_zb[HB];             // bf16 zeros
__device__ float g_c0[HB];
__device__ float g_c1[HB];
__device__ __nv_bfloat16 g_h1h[2 * HB], g_h1l[2 * HB];
__device__ __nv_bfloat16 g_h0h[2 * HB], g_h0l[2 * HB];
__device__ float g_h1f[HB];
__device__ float g_h0f[HB];                    // sink for layer0 fp32 h
// reordered (row = u*4+g) hi/lo weights
__device__ __nv_bfloat16 g_w0h[GROW * HID], g_w0l[GROW * HID];        // Whh0
__device__ __nv_bfloat16 g_w1hh_h[GROW * HID], g_w1hh_l[GROW * HID];  // Whh1
__device__ __nv_bfloat16 g_w1ih_h[GROW * HID], g_w1ih_l[GROW * HID];  // Wih1
__device__ __nv_bfloat16 g_wx0h[GROW * XPW], g_wx0l[GROW * XPW];      // Wih0 padded
__device__ float g_br0[GROW], g_br1[GROW];

// ---------------------------------------------------------------------------
// Portable PTX helpers (sm_80+ only)
// ---------------------------------------------------------------------------
__device__ __forceinline__ uint32_t smem_u32(const void* p) {
    uint32_t a;
    asm("{ .reg .u64 t; cvta.to.shared.u64 t, %1; cvt.u32.u64 %0, t; }"
        : "=r"(a) : "l"(p));
    return a;
}
#define CP_ASYNC16(dst, src) \
    asm volatile("cp.async.cg.shared.global [%0], [%1], 16;" \
                 :: "r"(dst), "l"(src) : "memory")
#define CP_COMMIT() asm volatile("cp.async.commit_group;" ::: "memory")
#define CP_WAIT1()  asm volatile("cp.async.wait_group 1;" ::: "memory")
#define CP_WAIT0()  asm volatile("cp.async.wait_group 0;" ::: "memory")

#define LDM4(r, addr) \
    asm volatile("ldmatrix.sync.aligned.m8n8.x4.shared.b16 {%0,%1,%2,%3}, [%4];" \
                 : "=r"((r)[0]), "=r"((r)[1]), "=r"((r)[2]), "=r"((r)[3]) \
                 : "r"(addr))

#define MMA16816(d, a, b0, b1) \
    asm volatile( \
        "mma.sync.aligned.m16n8k16.row.col.f32.bf16.bf16.f32 " \
        "{%0,%1,%2,%3}, {%4,%5,%6,%7}, {%8,%9}, {%0,%1,%2,%3};" \
        : "+f"((d)[0]), "+f"((d)[1]), "+f"((d)[2]), "+f"((d)[3]) \
        : "r"((a)[0]), "r"((a)[1]), "r"((a)[2]), "r"((a)[3]), \
          "r"(b0), "r"(b1))

// ---------------------------------------------------------------------------
// SMEM: per-warp private slabs, 2 stages — NO CTA barriers in the main loop.
// Each warp owns 6144B per stage: [Ah 1536][Al 1536][Bh 1536][Bl 1536],
// each a 32-row x 16-col bf16 block at 48B row stride (16B-aligned).
// ---------------------------------------------------------------------------
#define SLAB_ROW 48
#define MAT_B 1536                        // 32 * 48
#define OFF_ah 0
#define OFF_al MAT_B
#define OFF_bh (2 * MAT_B)
#define OFF_bl (3 * MAT_B)
#define REG_B (4 * MAT_B)                 // 6144 per warp per stage
#define NST 2
#define OFF_BIAS (NST * 8 * REG_B)        // 98304
#define SMEM_TOTAL (OFF_BIAS + 64 * 4 + 16)   // 98576 -> 2 CTAs/SM
#define CPSTRIDE 36                       // fp32 partial-C row stride (per warp)

// ---------------------------------------------------------------------------
// Math helpers
// ---------------------------------------------------------------------------
__device__ __forceinline__ float sigmoidf_(float x) { return 1.0f / (1.0f + __expf(-x)); }
__device__ __forceinline__ float tanhf_(float x)    { return 2.0f / (1.0f + __expf(-2.0f * x)) - 1.0f; }
__device__ __forceinline__ void split2(float x, __nv_bfloat16& h, __nv_bfloat16& l) {
    h = __float2bfloat16(x);
    l = __float2bfloat16(x - __bfloat162float(h));
}

// ---------------------------------------------------------------------------
// prep: smoothing + padded-x hi/lo for encoder; decoder init at t=149
// ---------------------------------------------------------------------------
__global__ void prep_kernel(const float* __restrict__ veg,
                            const float* __restrict__ wh,
                            const float* __restrict__ wf,
                            __nv_bfloat16* __restrict__ xph,
                            __nv_bfloat16* __restrict__ xpl,
                            __nv_bfloat16* __restrict__ xdh,
                            __nv_bfloat16* __restrict__ xdl,
                            float* __restrict__ pred) {
    int b = threadIdx.x;
    int t = blockIdx.x;
    const int base = (t * NB + b) * XPW;
    float vs[VEG];
#pragma unroll
    for (int v = 0; v < VEG; v++) {
        float val = veg[b * (T_HIST * VEG) + t * VEG + v];
        float s = 0.f;
#pragma unroll
        for (int dt = -2; dt <= 2; dt++) {
            int tt = t + dt;
            if (tt >= 0 && tt < T_HIST) {
                float u = veg[b * (T_HIST * VEG) + tt * VEG + v];
                if (!isnan(u)) s += u;
            }
        }
        float sm = s * 0.2f;
        float outv = isnan(val) ? sm : val;
        if (isnan(outv)) outv = 0.f;
        vs[v] = outv;
        __nv_bfloat16 hh, ll; split2(outv, hh, ll);
        xph[base + v] = hh; xpl[base + v] = ll;
    }
#pragma unroll
    for (int k = 0; k < WEA; k++) {
        float w = wh[b * (T_HIST * WEA) + t * WEA + k];
        __nv_bfloat16 hh, ll; split2(w, hh, ll);
        xph[base + VEG + k] = hh; xpl[base + VEG + k] = ll;
    }
    __nv_bfloat16 z = __float2bfloat16(0.f);
    for (int c = VEG + WEA; c < XPW; c++) { xph[base + c] = z; xpl[base + c] = z; }

    if (t == T_HIST - 1) {
        int db = b * XPW;
#pragma unroll
        for (int v = 0; v < VEG; v++) {
            pred[b * VEG + v] = vs[v];
            __nv_bfloat16 hh, ll; split2(vs[v], hh, ll);
            xdh[db + v] = hh; xdl[db + v] = ll;
        }
#pragma unroll
        for (int k = 0; k < WEA; k++) {
            float w = wf[b * (T_FUT * WEA) + k];
            __nv_bfloat16 hh, ll; split2(w, hh, ll);
            xdh[db + VEG + k] = hh; xdl[db + VEG + k] = ll;
        }
        for (int c = VEG + WEA; c < XPW; c++) { xdh[db + c] = z; xdl[db + c] = z; }
    }
}

// ---------------------------------------------------------------------------
// weight prep: reorder rows to u*4+g, split hi/lo, pad Wih0 to 64 cols
// ---------------------------------------------------------------------------
__global__ void wprep_kernel(const float* __restrict__ Wih0, const float* __restrict__ Whh0,
                             const float* __restrict__ b0,   const float* __restrict__ Wih1,
                             const float* __restrict__ Whh1, const float* __restrict__ b1,
                             __nv_bfloat16* w0h, __nv_bfloat16* w0l,
                             __nv_bfloat16* w1hhh, __nv_bfloat16* w1hhl,
                             __nv_bfloat16* w1ihh, __nv_bfloat16* w1ihl,
                             __nv_bfloat16* wx0h, __nv_bfloat16* wx0l,
                             float* br0, float* br1) {
    int rn = blockIdx.x;                       // new row
    int orig = (rn & 3) * HID + (rn >> 2);     // g*512 + u
    for (int c = threadIdx.x; c < HID; c += blockDim.x) {
        __nv_bfloat16 hh, ll;
        split2(Whh0[orig * HID + c], hh, ll);
        w0h[rn * HID + c] = hh; w0l[rn * HID + c] = ll;
        split2(Whh1[orig * HID + c], hh, ll);
        w1hhh[rn * HID + c] = hh; w1hhl[rn * HID + c] = ll;
        split2(Wih1[orig * HID + c], hh, ll);
        w1ihh[rn * HID + c] = hh; w1ihl[rn * HID + c] = ll;
    }
    if (threadIdx.x < XPW) {
        int c = threadIdx.x;
        float v = (c < VEG + WEA) ? Wih0[orig * (VEG + WEA) + c] : 0.f;
        __nv_bfloat16 hh, ll; split2(v, hh, ll);
        wx0h[rn * XPW + c] = hh; wx0l[rn * XPW + c] = ll;
    }
    if (threadIdx.x == 0) { br0[rn] = b0[orig]; br1[rn] = b1[orig]; }
}

__global__ void zero_kernel(float* __restrict__ c0, float* __restrict__ c1,
                            __nv_bfloat16* __restrict__ zb) {
    int i = blockIdx.x * blockDim.x + threadIdx.x;
    if (i < HB) { c0[i] = 0.f; c1[i] = 0.f; zb[i] = __float2bfloat16(0.f); }
}

// ---------------------------------------------------------------------------
// Cell body: 32(batch)x64(gate) tile. 8 warps = 4 K-groups x 2 N-halves,
// warp tile 32x32. Each warp runs a PRIVATE cp.async pipeline into its own
// smem slab — zero CTA barriers in the main loop. One __syncthreads before
// the cross-warp K reduction in the epilogue.
// ---------------------------------------------------------------------------
__device__ __forceinline__ void cell_body(
    char* smem, int m0, int tileY,
    const __nv_bfloat16* __restrict__ AhH, const __nv_bfloat16* __restrict__ AhL,
    const __nv_bfloat16* __restrict__ BhH, const __nv_bfloat16* __restrict__ BhL,
    const __nv_bfloat16* __restrict__ AxH, const __nv_bfloat16* __restrict__ AxL,
    const __nv_bfloat16* __restrict__ BxH, const __nv_bfloat16* __restrict__ BxL,
    int ncx, int ldx,
    const float* __restrict__ biasr,
    float* __restrict__ c, float* __restrict__ hf,
    __nv_bfloat16* __restrict__ hhi, __nv_bfloat16* __restrict__ hlo) {

    const uint32_t sbase = smem_u32(smem);
    const int tid = threadIdx.x;
    const int warp = tid >> 5;
    const int lane = tid & 31;
    const int n0 = tileY * 64;            // reordered weight row base
    const int u0 = tileY * 16;            // unit base
    const int ks = warp & 3;              // K-group (16-col slice of 64-chunk)
    const int wn = warp >> 2;             // 0..1 N-half (32 gate cols)

    if (tid < 64)
        *reinterpret_cast<float*>(smem + OFF_BIAS + tid * 4) = biasr[n0 + tid];

    float cfr[2][4][4];   // hi*hi
    float cfl[2][4][4];   // hi*lo + lo*hi
#pragma unroll
    for (int mi = 0; mi < 2; mi++)
#pragma unroll
        for (int nj = 0; nj < 4; nj++)
#pragma unroll
            for (int r = 0; r < 4; r++) { cfr[mi][nj][r] = 0.f; cfl[mi][nj][r] = 0.f; }

    const int NC = 8 + ncx;
    const int nrow = n0 + wn * 32 + lane;     // this lane's B row
    const int arow = m0 + lane;               // this lane's A row
    const uint32_t dst_a = lane * SLAB_ROW;   // slab-relative dst for this lane

    // per-warp prefetch of chunk ch into stage ch&1 of this warp's slab
    auto pf = [&](int ch) {
        const __nv_bfloat16 *aH, *aL, *bH, *bL;
        int lda, k0;
        if (ch < 8) { aH = AhH; aL = AhL; bH = BhH; bL = BhL; lda = HID; k0 = ch * 64; }
        else        { aH = AxH; aL = AxL; bH = BxH; bL = BxL; lda = ldx; k0 = (ch - 8) * 64; }
        const int col = k0 + ks * 16;
        const uint32_t st = sbase + ((uint32_t)((ch & 1) * 8 + warp)) * REG_B;
        long ao = (long)arow * lda + col;
        long bo = (long)nrow * lda + col;
        CP_ASYNC16(st + OFF_ah + dst_a,      aH + ao);
        CP_ASYNC16(st + OFF_ah + dst_a + 16, aH + ao + 8);
        CP_ASYNC16(st + OFF_al + dst_a,      aL + ao);
        CP_ASYNC16(st + OFF_al + dst_a + 16, aL + ao + 8);
        CP_ASYNC16(st + OFF_bh + dst_a,      bH + bo);
        CP_ASYNC16(st + OFF_bh + dst_a + 16, bH + bo + 8);
        CP_ASYNC16(st + OFF_bl + dst_a,      bL + bo);
        CP_ASYNC16(st + OFF_bl + dst_a + 16, bL + bo + 8);
    };

    pf(0); CP_COMMIT();
    pf(1); CP_COMMIT();

    const uint32_t ldrow = (uint32_t)((lane & 15) * SLAB_ROW + (lane >> 4) * 16);

    for (int ch = 0; ch < NC; ch++) {
        if (ch + 1 < NC) CP_WAIT1(); else CP_WAIT0();
        __syncwarp();    // make this warp's async smem writes warp-visible

        const uint32_t base = sbase + ((uint32_t)((ch & 1) * 8 + warp)) * REG_B;
        uint32_t ah[2][4], al[2][4], bh[4][2], bl[4][2];
#pragma unroll
        for (int mi = 0; mi < 2; mi++) {
            uint32_t roff = base + mi * (16 * SLAB_ROW) + ldrow;
            LDM4(ah[mi], roff + OFF_ah);
            LDM4(al[mi], roff + OFF_al);
        }
#pragma unroll
        for (int p = 0; p < 2; p++) {
            uint32_t roff = base + p * (16 * SLAB_ROW) + ldrow;
            uint32_t rb[4], rl[4];
            LDM4(rb, roff + OFF_bh);
            LDM4(rl, roff + OFF_bl);
            bh[p * 2 + 0][0] = rb[0]; bh[p * 2 + 0][1] = rb[2];
            bh[p * 2 + 1][0] = rb[1]; bh[p * 2 + 1][1] = rb[3];
            bl[p * 2 + 0][0] = rl[0]; bl[p * 2 + 0][1] = rl[2];
            bl[p * 2 + 1][0] = rl[1]; bl[p * 2 + 1][1] = rl[3];
        }
#pragma unroll
        for (int mi = 0; mi < 2; mi++)
#pragma unroll
            for (int nj = 0; nj < 4; nj++) {
                MMA16816(cfr[mi][nj], ah[mi], bh[nj][0], bh[nj][1]);
                MMA16816(cfl[mi][nj], ah[mi], bl[nj][0], bl[nj][1]);
                MMA16816(cfl[mi][nj], al[mi], bh[nj][0], bh[nj][1]);
            }

        if (ch + 2 < NC) { pf(ch + 2); CP_COMMIT(); }
    }

    // ---- epilogue: partial C into own slab (stage 0 region), then reduce ----
    {
        float* Cp = reinterpret_cast<float*>(smem + warp * REG_B);
#pragma unroll
        for (int mi = 0; mi < 2; mi++)
#pragma unroll
            for (int nj = 0; nj < 4; nj++) {
                int r = mi * 16 + (lane >> 2);
                int col = nj * 8 + (lane & 3) * 2;
                Cp[r * CPSTRIDE + col]           = cfr[mi][nj][0] + cfl[mi][nj][0];
                Cp[r * CPSTRIDE + col + 1]       = cfr[mi][nj][1] + cfl[mi][nj][1];
                Cp[(r + 8) * CPSTRIDE + col]     = cfr[mi][nj][2] + cfl[mi][nj][2];
                Cp[(r + 8) * CPSTRIDE + col + 1] = cfr[mi][nj][3] + cfl[mi][nj][3];
            }
    }
    __syncthreads();

    const float* Bs = reinterpret_cast<const float*>(smem + OFF_BIAS);
#pragma unroll
    for (int k = 0; k < 2; k++) {             // 512 (bb,u) pairs / 256 threads
        int id = tid + k * NTHREADS;
        int u = id & 15, bb = id >> 4;        // bb 0..31
        int wsel = u >> 3;                    // N-half
        int colw = (u * 4) & 31;
        float4 g4 = make_float4(0.f, 0.f, 0.f, 0.f);
#pragma unroll
        for (int g = 0; g < 4; g++) {         // sum 4 K-group partials
            const float* Cp = reinterpret_cast<const float*>(
                smem + (g + 4 * wsel) * REG_B);
            float4 p4 = *reinterpret_cast<const float4*>(&Cp[bb * CPSTRIDE + colw]);
            g4.x += p4.x; g4.y += p4.y; g4.z += p4.z; g4.w += p4.w;
        }
        float gi = sigmoidf_(g4.x + Bs[u * 4 + 0]);
        float gf = sigmoidf_(g4.y + Bs[u * 4 + 1]);
        float gg = tanhf_   (g4.z + Bs[u * 4 + 2]);
        float go = sigmoidf_(g4.w + Bs[u * 4 + 3]);
        int gidx = (m0 + bb) * HID + u0 + u;
        float cn = gf * c[gidx] + gi * gg;
        c[gidx] = cn;
        float hv = go * tanhf_(cn);
        hf[gidx] = hv;
        __nv_bfloat16 hh, ll; split2(hv, hh, ll);
        hhi[gidx] = hh; hlo[gidx] = ll;
    }
}

// ---------------------------------------------------------------------------
// Single-cell kernel: grid (8, 32) = 256 CTAs, 2 CTAs/SM resident
// ---------------------------------------------------------------------------
__global__ void __launch_bounds__(NTHREADS, 2)
cell_mma(const __nv_bfloat16* __restrict__ AhH, const __nv_bfloat16* __restrict__ AhL,
         const __nv_bfloat16* __restrict__ BhH, const __nv_bfloat16* __restrict__ BhL,
         const __nv_bfloat16* __restrict__ AxH, const __nv_bfloat16* __restrict__ AxL,
         const __nv_bfloat16* __restrict__ BxH, const __nv_bfloat16* __restrict__ BxL,
         int ncx, int ldx,
         const float* __restrict__ biasr,
         float* __restrict__ c, float* __restrict__ hf,
         __nv_bfloat16* __restrict__ hhi, __nv_bfloat16* __restrict__ hlo) {
    extern __shared__ __align__(16) char smem[];
    cell_body(smem, blockIdx.x * 32, blockIdx.y,
              AhH, AhL, BhH, BhL, AxH, AxL, BxH, BxL,
              ncx, ldx, biasr, c, hf, hhi, hlo);
}

// ---------------------------------------------------------------------------
// Merged encoder wavefront step: grid (8, 64) = 512 CTAs (L1 y<32, L0 y>=32)
// ---------------------------------------------------------------------------
__global__ void __launch_bounds__(NTHREADS, 2)
enc_step(const __nv_bfloat16* __restrict__ h1pH, const __nv_bfloat16* __restrict__ h1pL,
         const __nv_bfloat16* __restrict__ w1hhh, const __nv_bfloat16* __restrict__ w1hhl,
         const __nv_bfloat16* __restrict__ y0tH, const __nv_bfloat16* __restrict__ y0tL,
         const __nv_bfloat16* __restrict__ w1ihh, const __nv_bfloat16* __restrict__ w1ihl,
         const float* __restrict__ br1, float* __restrict__ c1,
         float* __restrict__ h1f,
         __nv_bfloat16* __restrict__ h1oh, __nv_bfloat16* __restrict__ h1ol,
         const __nv_bfloat16* __restrict__ xnH, const __nv_bfloat16* __restrict__ xnL,
         const __nv_bfloat16* __restrict__ w0h, const __nv_bfloat16* __restrict__ w0l,
         const __nv_bfloat16* __restrict__ wx0h, const __nv_bfloat16* __restrict__ wx0l,
         const float* __restrict__ br0, float* __restrict__ c0,
         float* __restrict__ h0f,
         __nv_bfloat16* __restrict__ y0nH, __nv_bfloat16* __restrict__ y0nL) {
    extern __shared__ __align__(16) char smem[];
    const int m0 = blockIdx.x * 32;
    if (blockIdx.y < 32) {
        cell_body(smem, m0, blockIdx.y,
                  h1pH, h1pL, w1hhh, w1hhl, y0tH, y0tL, w1ihh, w1ihl,
                  8, HID, br1, c1, h1f, h1oh, h1ol);
    } else {
        cell_body(smem, m0, blockIdx.y - 32,
                  y0tH, y0tL, w0h, w0l, xnH, xnL, wx0h, wx0l,
                  1, XPW, br0, c0, h0f, y0nH, y0nL);
    }
}

// ---------------------------------------------------------------------------
// head: pred += h1 @ headW^T + headb ; write output[t]; build next decoder x
// ---------------------------------------------------------------------------
__global__ void head_kernel(const float* __restrict__ h1,
                            const float* __restrict__ headW,
                            const float* __restrict__ headb,
                            float* __restrict__ pred,
                            float* __restrict__ out_t,
                            const float* __restrict__ wf_next,
                            __nv_bfloat16* __restrict__ xdh,
                            __nv_bfloat16* __restrict__ xdl) {
    int b = blockIdx.x;
    int w = threadIdx.x >> 5;
    int lane = threadIdx.x & 31;
    const float* hr = &h1[b * HID];
    const float* wr = &headW[w * HID];
    float s = 0.f;
    for (int k = lane; k < HID; k += 32) s += hr[k] * wr[k];
#pragma unroll
    for (int o = 16; o; o >>= 1) s += __shfl_down_sync(0xffffffffu, s, o);
    if (lane == 0) {
        float p = pred[b * VEG + w] + s + headb[w];
        pred[b * VEG + w] = p;
        out_t[b * (T_FUT * VEG) + w] = p;
        __nv_bfloat16 hh, ll; split2(p, hh, ll);
        xdh[b * XPW + w] = hh; xdl[b * XPW + w] = ll;
    }
    if (threadIdx.x < WEA && wf_next) {
        float v = wf_next[b * (T_FUT * WEA) + threadIdx.x];
        __nv_bfloat16 hh, ll; split2(v, hh, ll);
        xdh[b * XPW + VEG + threadIdx.x] = hh;
        xdl[b * XPW + VEG + threadIdx.x] = ll;
    }
}

// ---------------------------------------------------------------------------
// Host launcher (single stream — graph-capture safe)
// ---------------------------------------------------------------------------
extern "C" void kernel_launch(void* const* d_in, const int* in_sizes, int n_in,
                              void* d_out, int out_size) {
    const float* veg   = (const float*)d_in[0];
    const float* wh    = (const float*)d_in[1];
    const float* wf    = (const float*)d_in[2];
    const float* Wih0  = (const float*)d_in[3];
    const float* Whh0  = (const float*)d_in[4];
    const float* b0    = (const float*)d_in[5];
    const float* Wih1  = (const float*)d_in[6];
    const float* Whh1  = (const float*)d_in[7];
    const float* b1    = (const float*)d_in[8];
    const float* headW = (const float*)d_in[9];
    const float* headb = (const float*)d_in[10];
    float* out = (float*)d_out;

    __nv_bfloat16 *xph, *xpl, *xdh, *xdl, *y0h, *y0l, *zb;
    __nv_bfloat16 *h1h, *h1l, *h0h, *h0l;
    __nv_bfloat16 *w0h, *w0l, *w1hhh, *w1hhl, *w1ihh, *w1ihl, *wx0h, *wx0l;
    float *pred, *c0, *c1, *h1f, *h0f, *br0, *br1;
    cudaGetSymbolAddress((void**)&xph,   g_xph);
    cudaGetSymbolAddress((void**)&xpl,   g_xpl);
    cudaGetSymbolAddress((void**)&xdh,   g_xdh);
    cudaGetSymbolAddress((void**)&xdl,   g_xdl);
    cudaGetSymbolAddress((void**)&pred,  g_pred);
    cudaGetSymbolAddress((void**)&y0h,   g_y0h);
    cudaGetSymbolAddress((void**)&y0l,   g_y0l);
    cudaGetSymbolAddress((void**)&zb,    g_zb);
    cudaGetSymbolAddress((void**)&c0,    g_c0);
    cudaGetSymbolAddress((void**)&c1,    g_c1);
    cudaGetSymbolAddress((void**)&h1h,   g_h1h);
    cudaGetSymbolAddress((void**)&h1l,   g_h1l);
    cudaGetSymbolAddress((void**)&h0h,   g_h0h);
    cudaGetSymbolAddress((void**)&h0l,   g_h0l);
    cudaGetSymbolAddress((void**)&h1f,   g_h1f);
    cudaGetSymbolAddress((void**)&h0f,   g_h0f);
    cudaGetSymbolAddress((void**)&w0h,   g_w0h);
    cudaGetSymbolAddress((void**)&w0l,   g_w0l);
    cudaGetSymbolAddress((void**)&w1hhh, g_w1hh_h);
    cudaGetSymbolAddress((void**)&w1hhl, g_w1hh_l);
    cudaGetSymbolAddress((void**)&w1ihh, g_w1ih_h);
    cudaGetSymbolAddress((void**)&w1ihl, g_w1ih_l);
    cudaGetSymbolAddress((void**)&wx0h,  g_wx0h);
    cudaGetSymbolAddress((void**)&wx0l,  g_wx0l);
    cudaGetSymbolAddress((void**)&br0,   g_br0);
    cudaGetSymbolAddress((void**)&br1,   g_br1);

    cudaFuncSetAttribute(cell_mma, cudaFuncAttributeMaxDynamicSharedMemorySize,
                         SMEM_TOTAL);
    cudaFuncSetAttribute(enc_step, cudaFuncAttributeMaxDynamicSharedMemorySize,
                         SMEM_TOTAL);

    dim3 grid1(8, 32), grid2(8, 64), blk(NTHREADS);

    prep_kernel<<<T_HIST, NB>>>(veg, wh, wf, xph, xpl, xdh, xdl, pred);
    wprep_kernel<<<GROW, 128>>>(Wih0, Whh0, b0, Wih1, Whh1, b1,
                                w0h, w0l, w1hhh, w1hhl, w1ihh, w1ihl,
                                wx0h, wx0l, br0, br1);
    zero_kernel<<<(HB + 255) / 256, 256>>>(c0, c1, zb);

    // L0(0) alone
    cell_mma<<<grid1, blk, SMEM_TOTAL>>>(
        zb, zb, w0h, w0l, xph, xpl, wx0h, wx0l,
        1, XPW, br0, c0, h0f, y0h, y0l);

    // merged wavefront: t = 0..148 computes L1(t) and L0(t+1) concurrently
    for (int t = 0; t < T_HIST - 1; t++) {
        const __nv_bfloat16* h1pH = (t == 0) ? zb : (h1h + ((t + 1) & 1) * HB);
        const __nv_bfloat16* h1pL = (t == 0) ? zb : (h1l + ((t + 1) & 1) * HB);
        enc_step<<<grid2, blk, SMEM_TOTAL>>>(
            h1pH, h1pL, w1hhh, w1hhl,
            y0h + (size_t)t * HB, y0l + (size_t)t * HB, w1ihh, w1ihl,
            br1, c1, h1f, h1h + (t & 1) * HB, h1l + (t & 1) * HB,
            xph + (size_t)(t + 1) * NB * XPW, xpl + (size_t)(t + 1) * NB * XPW,
            w0h, w0l, wx0h, wx0l,
            br0, c0, h0f,
            y0h + (size_t)(t + 1) * HB, y0l + (size_t)(t + 1) * HB);
    }
    // final L1(149): reads h1[148&1=0], writes h1[149&1=1]
    {
        int t = T_HIST - 1;
        cell_mma<<<grid1, blk, SMEM_TOTAL>>>(
            h1h + ((t + 1) & 1) * HB, h1l + ((t + 1) & 1) * HB, w1hhh, w1hhl,
            y0h + (size_t)t * HB, y0l + (size_t)t * HB, w1ihh, w1ihl,
            8, HID, br1, c1, h1f, h1h + (t & 1) * HB, h1l + (t & 1) * HB);
    }

    // decoder (serial dependence); h1 phases: read (t+1)&1, write t&1
    for (int t = 0; t < T_FUT; t++) {
        const __nv_bfloat16* hpH = (t == 0) ? (y0h + (size_t)(T_HIST - 1) * HB)
                                            : (h0h + ((t + 1) & 1) * HB);
        const __nv_bfloat16* hpL = (t == 0) ? (y0l + (size_t)(T_HIST - 1) * HB)
                                            : (h0l + ((t + 1) & 1) * HB);
        cell_mma<<<grid1, blk, SMEM_TOTAL>>>(
            hpH, hpL, w0h, w0l, xdh, xdl, wx0h, wx0l,
            1, XPW, br0, c0, h0f, h0h + (t & 1) * HB, h0l + (t & 1) * HB);
        cell_mma<<<grid1, blk, SMEM_TOTAL>>>(
            h1h + ((t + 1) & 1) * HB, h1l + ((t + 1) & 1) * HB, w1hhh, w1hhl,
            h0h + (t & 1) * HB, h0l + (t & 1) * HB, w1ihh, w1ihl,
            8, HID, br1, c1, h1f, h1h + (t & 1) * HB, h1l + (t & 1) * HB);
        const float* wfn = (t < T_FUT - 1) ? (wf + (t + 1) * WEA) : nullptr;
        head_kernel<<<NB, 128>>>(h1f, headW, headb, pred,
                                 out + t * VEG, wfn, xdh, xdl);
    }
}

// round 12
// speedup vs baseline: 1.9896x; 1.9896x over previous
#include <cuda_runtime.h>
#include <cuda_bf16.h>
#include <cstdint>
#include <math.h>

// ---------------------------------------------------------------------------
// Problem constants
// ---------------------------------------------------------------------------
#define VEG 4
#define WEA 8
#define HID 512
#define NB  256
#define T_HIST 150
#define T_FUT  50
#define HB (NB * HID)
#define XPW 64            // padded x width (12 real + 52 zeros)
#define GROW 2048         // gate rows (4*HID)
#define NTHREADS 256      // 8 warps per CTA, occupancy 2

// ---------------------------------------------------------------------------
// Device scratch (static only)
// ---------------------------------------------------------------------------
__device__ __nv_bfloat16 g_xph[T_HIST * NB * XPW];
__device__ __nv_bfloat16 g_xpl[T_HIST * NB * XPW];
__device__ __nv_bfloat16 g_xdh[NB * XPW];
__device__ __nv_bfloat16 g_xdl[NB * XPW];
__device__ float g_pred[NB * VEG];
__device__ __nv_bfloat16 g_y0h[T_HIST * HB];   // layer0 outputs hi (h-chain)
__device__ __nv_bfloat16 g_y0l[T_HIST * HB];
__device__ __nv_bfloat16 g_zb[HB];             // bf16 zeros
__device__ float g_c0[HB];
__device__ float g_c1[HB];
__device__ __nv_bfloat16 g_h1h[2 * HB], g_h1l[2 * HB];
__device__ __nv_bfloat16 g_h0h[2 * HB], g_h0l[2 * HB];
__device__ float g_h1f[HB];
__device__ float g_h0f[HB];                    // sink for layer0 fp32 h
// reordered (row = u*4+g) hi/lo weights
__device__ __nv_bfloat16 g_w0h[GROW * HID], g_w0l[GROW * HID];        // Whh0
__device__ __nv_bfloat16 g_w1hh_h[GROW * HID], g_w1hh_l[GROW * HID];  // Whh1
__device__ __nv_bfloat16 g_w1ih_h[GROW * HID], g_w1ih_l[GROW * HID];  // Wih1
__device__ __nv_bfloat16 g_wx0h[GROW * XPW], g_wx0l[GROW * XPW];      // Wih0 padded
__device__ float g_br0[GROW], g_br1[GROW];

// ---------------------------------------------------------------------------
// Portable PTX helpers (sm_80+ only)
// ---------------------------------------------------------------------------
__device__ __forceinline__ uint32_t smem_u32(const void* p) {
    uint32_t a;
    asm("{ .reg .u64 t; cvta.to.shared.u64 t, %1; cvt.u32.u64 %0, t; }"
        : "=r"(a) : "l"(p));
    return a;
}
#define CP_ASYNC16(dst, src) \
    asm volatile("cp.async.cg.shared.global [%0], [%1], 16;" \
                 :: "r"(dst), "l"(src) : "memory")
#define CP_COMMIT() asm volatile("cp.async.commit_group;" ::: "memory")
#define CP_WAIT1()  asm volatile("cp.async.wait_group 1;" ::: "memory")
#define CP_WAIT0()  asm volatile("cp.async.wait_group 0;" ::: "memory")

#define LDM4(r, addr) \
    asm volatile("ldmatrix.sync.aligned.m8n8.x4.shared.b16 {%0,%1,%2,%3}, [%4];" \
                 : "=r"((r)[0]), "=r"((r)[1]), "=r"((r)[2]), "=r"((r)[3]) \
                 : "r"(addr))

#define MMA16816(d, a, b0, b1) \
    asm volatile( \
        "mma.sync.aligned.m16n8k16.row.col.f32.bf16.bf16.f32 " \
        "{%0,%1,%2,%3}, {%4,%5,%6,%7}, {%8,%9}, {%0,%1,%2,%3};" \
        : "+f"((d)[0]), "+f"((d)[1]), "+f"((d)[2]), "+f"((d)[3]) \
        : "r"((a)[0]), "r"((a)[1]), "r"((a)[2]), "r"((a)[3]), \
          "r"(b0), "r"(b1))

// ---------------------------------------------------------------------------
// SMEM layout (parameterized by M tile)
// ---------------------------------------------------------------------------
#define SM_STRIDE 72                        // bf16 elems/row (144B, conflict-free)
#define ROW_B (SM_STRIDE * 2)               // 144 bytes
#define B_TILE_BYTES (64 * ROW_B)           // 9216
#define NSTAGE 3
#define CS_STRIDE 68                        // fp32 C tile row stride

#define A_TILE_BYTES_(MT) ((MT) * ROW_B)
#define STAGE_BYTES_(MT)  (2 * A_TILE_BYTES_(MT) + 2 * B_TILE_BYTES)
#define OFF_BIAS_(MT)     (NSTAGE * STAGE_BYTES_(MT))
#define SMEM_TOTAL_(MT)   (OFF_BIAS_(MT) + 64 * 4 + 16)
// MT=32: stage 27648, total 83216 (2/SM = 166KB, fits 227KB)

// ---------------------------------------------------------------------------
// Math helpers
// ---------------------------------------------------------------------------
__device__ __forceinline__ float sigmoidf_(float x) { return 1.0f / (1.0f + __expf(-x)); }
__device__ __forceinline__ float tanhf_(float x)    { return 2.0f / (1.0f + __expf(-2.0f * x)) - 1.0f; }
__device__ __forceinline__ void split2(float x, __nv_bfloat16& h, __nv_bfloat16& l) {
    h = __float2bfloat16(x);
    l = __float2bfloat16(x - __bfloat162float(h));
}

// ---------------------------------------------------------------------------
// prep: smoothing + padded-x hi/lo for encoder; decoder init at t=149
// ---------------------------------------------------------------------------
__global__ void prep_kernel(const float* __restrict__ veg,
                            const float* __restrict__ wh,
                            const float* __restrict__ wf,
                            __nv_bfloat16* __restrict__ xph,
                            __nv_bfloat16* __restrict__ xpl,
                            __nv_bfloat16* __restrict__ xdh,
                            __nv_bfloat16* __restrict__ xdl,
                            float* __restrict__ pred) {
    int b = threadIdx.x;
    int t = blockIdx.x;
    const int base = (t * NB + b) * XPW;
    float vs[VEG];
#pragma unroll
    for (int v = 0; v < VEG; v++) {
        float val = veg[b * (T_HIST * VEG) + t * VEG + v];
        float s = 0.f;
#pragma unroll
        for (int dt = -2; dt <= 2; dt++) {
            int tt = t + dt;
            if (tt >= 0 && tt < T_HIST) {
                float u = veg[b * (T_HIST * VEG) + tt * VEG + v];
                if (!isnan(u)) s += u;
            }
        }
        float sm = s * 0.2f;
        float outv = isnan(val) ? sm : val;
        if (isnan(outv)) outv = 0.f;
        vs[v] = outv;
        __nv_bfloat16 hh, ll; split2(outv, hh, ll);
        xph[base + v] = hh; xpl[base + v] = ll;
    }
#pragma unroll
    for (int k = 0; k < WEA; k++) {
        float w = wh[b * (T_HIST * WEA) + t * WEA + k];
        __nv_bfloat16 hh, ll; split2(w, hh, ll);
        xph[base + VEG + k] = hh; xpl[base + VEG + k] = ll;
    }
    __nv_bfloat16 z = __float2bfloat16(0.f);
    for (int c = VEG + WEA; c < XPW; c++) { xph[base + c] = z; xpl[base + c] = z; }

    if (t == T_HIST - 1) {
        int db = b * XPW;
#pragma unroll
        for (int v = 0; v < VEG; v++) {
            pred[b * VEG + v] = vs[v];
            __nv_bfloat16 hh, ll; split2(vs[v], hh, ll);
            xdh[db + v] = hh; xdl[db + v] = ll;
        }
#pragma unroll
        for (int k = 0; k < WEA; k++) {
            float w = wf[b * (T_FUT * WEA) + k];
            __nv_bfloat16 hh, ll; split2(w, hh, ll);
            xdh[db + VEG + k] = hh; xdl[db + VEG + k] = ll;
        }
        for (int c = VEG + WEA; c < XPW; c++) { xdh[db + c] = z; xdl[db + c] = z; }
    }
}

// ---------------------------------------------------------------------------
// weight prep: reorder rows to u*4+g, split hi/lo, pad Wih0 to 64 cols
// ---------------------------------------------------------------------------
__global__ void wprep_kernel(const float* __restrict__ Wih0, const float* __restrict__ Whh0,
                             const float* __restrict__ b0,   const float* __restrict__ Wih1,
                             const float* __restrict__ Whh1, const float* __restrict__ b1,
                             __nv_bfloat16* w0h, __nv_bfloat16* w0l,
                             __nv_bfloat16* w1hhh, __nv_bfloat16* w1hhl,
                             __nv_bfloat16* w1ihh, __nv_bfloat16* w1ihl,
                             __nv_bfloat16* wx0h, __nv_bfloat16* wx0l,
                             float* br0, float* br1) {
    int rn = blockIdx.x;                       // new row
    int orig = (rn & 3) * HID + (rn >> 2);     // g*512 + u
    for (int c = threadIdx.x; c < HID; c += blockDim.x) {
        __nv_bfloat16 hh, ll;
        split2(Whh0[orig * HID + c], hh, ll);
        w0h[rn * HID + c] = hh; w0l[rn * HID + c] = ll;
        split2(Whh1[orig * HID + c], hh, ll);
        w1hhh[rn * HID + c] = hh; w1hhl[rn * HID + c] = ll;
        split2(Wih1[orig * HID + c], hh, ll);
        w1ihh[rn * HID + c] = hh; w1ihl[rn * HID + c] = ll;
    }
    if (threadIdx.x < XPW) {
        int c = threadIdx.x;
        float v = (c < VEG + WEA) ? Wih0[orig * (VEG + WEA) + c] : 0.f;
        __nv_bfloat16 hh, ll; split2(v, hh, ll);
        wx0h[rn * XPW + c] = hh; wx0l[rn * XPW + c] = ll;
    }
    if (threadIdx.x == 0) { br0[rn] = b0[orig]; br1[rn] = b1[orig]; }
}

__global__ void zero_kernel(float* __restrict__ c0, float* __restrict__ c1,
                            __nv_bfloat16* __restrict__ zb) {
    int i = blockIdx.x * blockDim.x + threadIdx.x;
    if (i < HB) { c0[i] = 0.f; c1[i] = 0.f; zb[i] = __float2bfloat16(0.f); }
}

// ---------------------------------------------------------------------------
// Cell body (R10-proven): one MT(batch)x64(gate) tile on HMMA.
// 8 warps: (MT/32) M x 2 N x KS K-groups, warp tile 32x32.
// MT=32 -> KS=4 (KITER=1). 3-stage cp.async pipeline, shared smem staging,
// per-K-group C slabs summed in the epilogue.
// ---------------------------------------------------------------------------
template <int MT>
__device__ __forceinline__ void cell_body(
    char* smem, int m0, int tileY,
    const __nv_bfloat16* __restrict__ AhH, const __nv_bfloat16* __restrict__ AhL,
    const __nv_bfloat16* __restrict__ BhH, const __nv_bfloat16* __restrict__ BhL,
    const __nv_bfloat16* __restrict__ AxH, const __nv_bfloat16* __restrict__ AxL,
    const __nv_bfloat16* __restrict__ BxH, const __nv_bfloat16* __restrict__ BxL,
    int ncx, int ldx,
    const float* __restrict__ biasr,
    float* __restrict__ c, float* __restrict__ hf,
    __nv_bfloat16* __restrict__ hhi, __nv_bfloat16* __restrict__ hlo) {

    constexpr int A_TILE = A_TILE_BYTES_(MT);
    constexpr int STAGE  = STAGE_BYTES_(MT);
    constexpr int OFF_AH = 0;
    constexpr int OFF_AL = A_TILE;
    constexpr int OFF_BH = 2 * A_TILE;
    constexpr int OFF_BL = 2 * A_TILE + B_TILE_BYTES;
    constexpr int OFF_BIAS = OFF_BIAS_(MT);
    constexpr int WM = MT / 32;           // M warp-slices (1 or 2)
    constexpr int KS = 8 / (WM * 2);      // K-groups (4 or 2)
    constexpr int KITER = 4 / KS;         // kk slices per warp per chunk
    constexpr int CSLAB = MT * CS_STRIDE; // floats per K-group C slab
    static_assert(WM * 2 * KS == 8, "warp layout");

    const uint32_t sbase = smem_u32(smem);
    const int tid = threadIdx.x;
    const int warp = tid >> 5;
    const int lane = tid & 31;
    const int n0 = tileY * 64;            // reordered weight row base
    const int u0 = tileY * 16;            // unit base
    const int ks = warp % KS;
    const int rem = warp / KS;
    const int wn = rem & 1;               // 0..1 (32-col slices)
    const int wm = rem >> 1;              // 0..WM-1 (32-row slices)

    if (tid < 64)
        *reinterpret_cast<float*>(smem + OFF_BIAS + tid * 4) = biasr[n0 + tid];

    float cfr[2][4][4];   // hi*hi
    float cfl[2][4][4];   // hi*lo + lo*hi
#pragma unroll
    for (int mi = 0; mi < 2; mi++)
#pragma unroll
        for (int nj = 0; nj < 4; nj++)
#pragma unroll
            for (int r = 0; r < 4; r++) { cfr[mi][nj][r] = 0.f; cfl[mi][nj][r] = 0.f; }

    const int NC = 8 + ncx;

    auto prefetch = [&](int ch) {
        const __nv_bfloat16 *aH, *aL, *bH, *bL;
        int lda, k0;
        if (ch < 8) { aH = AhH; aL = AhL; bH = BhH; bL = BhL; lda = HID; k0 = ch * 64; }
        else        { aH = AxH; aL = AxL; bH = BxH; bL = BxL; lda = ldx; k0 = (ch - 8) * 64; }
        const uint32_t st = sbase + (ch % NSTAGE) * STAGE;
        // A: MT rows x 64 bf16 (MT*8 16B chunks), hi + lo
#pragma unroll
        for (int i = 0; i < (MT * 8) / NTHREADS; i++) {
            int idx = tid + i * NTHREADS;
            int r = idx >> 3, q = idx & 7;
            uint32_t off = r * ROW_B + q * 16;
            long ao = (long)(m0 + r) * lda + k0 + q * 8;
            CP_ASYNC16(st + OFF_AH + off, aH + ao);
            CP_ASYNC16(st + OFF_AL + off, aL + ao);
        }
        // B: 64 rows x 64 bf16 (512 16B chunks), hi + lo
#pragma unroll
        for (int i = 0; i < 512 / NTHREADS; i++) {
            int idx = tid + i * NTHREADS;
            int r = idx >> 3, q = idx & 7;
            uint32_t off = r * ROW_B + q * 16;
            long bo = (long)(n0 + r) * lda + k0 + q * 8;
            CP_ASYNC16(st + OFF_BH + off, bH + bo);
            CP_ASYNC16(st + OFF_BL + off, bL + bo);
        }
    };

    prefetch(0); CP_COMMIT();
    prefetch(1); CP_COMMIT();

    for (int ch = 0; ch < NC; ch++) {
        if (ch + 1 < NC) CP_WAIT1(); else CP_WAIT0();
        __syncthreads();                    // publishes chunk ch
        if (ch + 2 < NC) { prefetch(ch + 2); CP_COMMIT(); }

        const uint32_t base = sbase + (ch % NSTAGE) * STAGE;
#pragma unroll
        for (int ki = 0; ki < KITER; ki++) {
            const int kk = (ks * KITER + ki) * 16;
            uint32_t ah[2][4], al[2][4], bh[4][2], bl[4][2];
#pragma unroll
            for (int mi = 0; mi < 2; mi++) {
                uint32_t roff =
                    (uint32_t)((wm * 32 + mi * 16 + (lane & 15)) * ROW_B +
                               (kk + (lane >> 4) * 8) * 2);
                LDM4(ah[mi], base + OFF_AH + roff);
                LDM4(al[mi], base + OFF_AL + roff);
            }
#pragma unroll
            for (int p = 0; p < 2; p++) {
                uint32_t roff =
                    (uint32_t)((wn * 32 + p * 16 + (lane & 15)) * ROW_B +
                               (kk + (lane >> 4) * 8) * 2);
                uint32_t rb[4], rl[4];
                LDM4(rb, base + OFF_BH + roff);
                LDM4(rl, base + OFF_BL + roff);
                bh[p * 2 + 0][0] = rb[0]; bh[p * 2 + 0][1] = rb[2];
                bh[p * 2 + 1][0] = rb[1]; bh[p * 2 + 1][1] = rb[3];
                bl[p * 2 + 0][0] = rl[0]; bl[p * 2 + 0][1] = rl[2];
                bl[p * 2 + 1][0] = rl[1]; bl[p * 2 + 1][1] = rl[3];
            }
#pragma unroll
            for (int mi = 0; mi < 2; mi++)
#pragma unroll
                for (int nj = 0; nj < 4; nj++) {
                    MMA16816(cfr[mi][nj], ah[mi], bh[nj][0], bh[nj][1]);
                    MMA16816(cfl[mi][nj], ah[mi], bl[nj][0], bl[nj][1]);
                    MMA16816(cfl[mi][nj], al[mi], bh[nj][0], bh[nj][1]);
                }
        }
    }
    __syncthreads();   // all ldmatrix reads done before Cs overwrites stage 0

    // ---- epilogue: per-K-group C slabs (single barrier) ----
    float* Cs = reinterpret_cast<float*>(smem);   // KS slabs of MT x CS_STRIDE
    {
        float* Cg = Cs + ks * CSLAB;
#pragma unroll
        for (int mi = 0; mi < 2; mi++)
#pragma unroll
            for (int nj = 0; nj < 4; nj++) {
                int r = wm * 32 + mi * 16 + (lane >> 2);
                int col = wn * 32 + nj * 8 + (lane & 3) * 2;
                Cg[r * CS_STRIDE + col]           = cfr[mi][nj][0] + cfl[mi][nj][0];
                Cg[r * CS_STRIDE + col + 1]       = cfr[mi][nj][1] + cfl[mi][nj][1];
                Cg[(r + 8) * CS_STRIDE + col]     = cfr[mi][nj][2] + cfl[mi][nj][2];
                Cg[(r + 8) * CS_STRIDE + col + 1] = cfr[mi][nj][3] + cfl[mi][nj][3];
            }
    }
    __syncthreads();

    const float* Bs = reinterpret_cast<const float*>(smem + OFF_BIAS);
#pragma unroll
    for (int k = 0; k < (MT * 16) / NTHREADS; k++) {
        int id = tid + k * NTHREADS;
        int u = id & 15, bb = id >> 4;        // bb 0..MT-1
        float4 g4 = *reinterpret_cast<const float4*>(&Cs[bb * CS_STRIDE + u * 4]);
#pragma unroll
        for (int g = 1; g < (8 / ((MT / 32) * 2)); g++) {
            float4 p4 = *reinterpret_cast<const float4*>(
                &Cs[g * CSLAB + bb * CS_STRIDE + u * 4]);
            g4.x += p4.x; g4.y += p4.y; g4.z += p4.z; g4.w += p4.w;
        }
        float gi = sigmoidf_(g4.x + Bs[u * 4 + 0]);
        float gf = sigmoidf_(g4.y + Bs[u * 4 + 1]);
        float gg = tanhf_   (g4.z + Bs[u * 4 + 2]);
        float go = sigmoidf_(g4.w + Bs[u * 4 + 3]);
        int gidx = (m0 + bb) * HID + u0 + u;
        float cn = gf * c[gidx] + gi * gg;
        c[gidx] = cn;
        float hv = go * tanhf_(cn);
        hf[gidx] = hv;
        __nv_bfloat16 hh, ll; split2(hv, hh, ll);
        hhi[gidx] = hh; hlo[gidx] = ll;
    }
}

// ---------------------------------------------------------------------------
// Single-cell kernel: MT=32, grid (8,32)=256 CTAs, 2 CTAs/SM resident
// ---------------------------------------------------------------------------
__global__ void __launch_bounds__(NTHREADS, 2)
cell_mma(const __nv_bfloat16* __restrict__ AhH, const __nv_bfloat16* __restrict__ AhL,
         const __nv_bfloat16* __restrict__ BhH, const __nv_bfloat16* __restrict__ BhL,
         const __nv_bfloat16* __restrict__ AxH, const __nv_bfloat16* __restrict__ AxL,
         const __nv_bfloat16* __restrict__ BxH, const __nv_bfloat16* __restrict__ BxL,
         int ncx, int ldx,
         const float* __restrict__ biasr,
         float* __restrict__ c, float* __restrict__ hf,
         __nv_bfloat16* __restrict__ hhi, __nv_bfloat16* __restrict__ hlo) {
    extern __shared__ __align__(16) char smem[];
    cell_body<32>(smem, blockIdx.x * 32, blockIdx.y,
                  AhH, AhL, BhH, BhL, AxH, AxL, BxH, BxL,
                  ncx, ldx, biasr, c, hf, hhi, hlo);
}

// ---------------------------------------------------------------------------
// Merged encoder wavefront step: MT=32, grid (8,64)=512 CTAs (work-stolen
// over 296 resident slots at 2/SM). L1(t) y<32, L0(t+1) y>=32.
// ---------------------------------------------------------------------------
__global__ void __launch_bounds__(NTHREADS, 2)
enc_step(const __nv_bfloat16* __restrict__ h1pH, const __nv_bfloat16* __restrict__ h1pL,
         const __nv_bfloat16* __restrict__ w1hhh, const __nv_bfloat16* __restrict__ w1hhl,
         const __nv_bfloat16* __restrict__ y0tH, const __nv_bfloat16* __restrict__ y0tL,
         const __nv_bfloat16* __restrict__ w1ihh, const __nv_bfloat16* __restrict__ w1ihl,
         const float* __restrict__ br1, float* __restrict__ c1,
         float* __restrict__ h1f,
         __nv_bfloat16* __restrict__ h1oh, __nv_bfloat16* __restrict__ h1ol,
         const __nv_bfloat16* __restrict__ xnH, const __nv_bfloat16* __restrict__ xnL,
         const __nv_bfloat16* __restrict__ w0h, const __nv_bfloat16* __restrict__ w0l,
         const __nv_bfloat16* __restrict__ wx0h, const __nv_bfloat16* __restrict__ wx0l,
         const float* __restrict__ br0, float* __restrict__ c0,
         float* __restrict__ h0f,
         __nv_bfloat16* __restrict__ y0nH, __nv_bfloat16* __restrict__ y0nL) {
    extern __shared__ __align__(16) char smem[];
    const int m0 = blockIdx.x * 32;
    if (blockIdx.y < 32) {
        cell_body<32>(smem, m0, blockIdx.y,
                      h1pH, h1pL, w1hhh, w1hhl, y0tH, y0tL, w1ihh, w1ihl,
                      8, HID, br1, c1, h1f, h1oh, h1ol);
    } else {
        cell_body<32>(smem, m0, blockIdx.y - 32,
                      y0tH, y0tL, w0h, w0l, xnH, xnL, wx0h, wx0l,
                      1, XPW, br0, c0, h0f, y0nH, y0nL);
    }
}

// ---------------------------------------------------------------------------
// head: pred += h1 @ headW^T + headb ; write output[t]; build next decoder x
// ---------------------------------------------------------------------------
__global__ void head_kernel(const float* __restrict__ h1,
                            const float* __restrict__ headW,
                            const float* __restrict__ headb,
                            float* __restrict__ pred,
                            float* __restrict__ out_t,
                            const float* __restrict__ wf_next,
                            __nv_bfloat16* __restrict__ xdh,
                            __nv_bfloat16* __restrict__ xdl) {
    int b = blockIdx.x;
    int w = threadIdx.x >> 5;
    int lane = threadIdx.x & 31;
    const float* hr = &h1[b * HID];
    const float* wr = &headW[w * HID];
    float s = 0.f;
    for (int k = lane; k < HID; k += 32) s += hr[k] * wr[k];
#pragma unroll
    for (int o = 16; o; o >>= 1) s += __shfl_down_sync(0xffffffffu, s, o);
    if (lane == 0) {
        float p = pred[b * VEG + w] + s + headb[w];
        pred[b * VEG + w] = p;
        out_t[b * (T_FUT * VEG) + w] = p;
        __nv_bfloat16 hh, ll; split2(p, hh, ll);
        xdh[b * XPW + w] = hh; xdl[b * XPW + w] = ll;
    }
    if (threadIdx.x < WEA && wf_next) {
        float v = wf_next[b * (T_FUT * WEA) + threadIdx.x];
        __nv_bfloat16 hh, ll; split2(v, hh, ll);
        xdh[b * XPW + VEG + threadIdx.x] = hh;
        xdl[b * XPW + VEG + threadIdx.x] = ll;
    }
}

// ---------------------------------------------------------------------------
// Host launcher (single stream — graph-capture safe)
// ---------------------------------------------------------------------------
extern "C" void kernel_launch(void* const* d_in, const int* in_sizes, int n_in,
                              void* d_out, int out_size) {
    const float* veg   = (const float*)d_in[0];
    const float* wh    = (const float*)d_in[1];
    const float* wf    = (const float*)d_in[2];
    const float* Wih0  = (const float*)d_in[3];
    const float* Whh0  = (const float*)d_in[4];
    const float* b0    = (const float*)d_in[5];
    const float* Wih1  = (const float*)d_in[6];
    const float* Whh1  = (const float*)d_in[7];
    const float* b1    = (const float*)d_in[8];
    const float* headW = (const float*)d_in[9];
    const float* headb = (const float*)d_in[10];
    float* out = (float*)d_out;

    __nv_bfloat16 *xph, *xpl, *xdh, *xdl, *y0h, *y0l, *zb;
    __nv_bfloat16 *h1h, *h1l, *h0h, *h0l;
    __nv_bfloat16 *w0h, *w0l, *w1hhh, *w1hhl, *w1ihh, *w1ihl, *wx0h, *wx0l;
    float *pred, *c0, *c1, *h1f, *h0f, *br0, *br1;
    cudaGetSymbolAddress((void**)&xph,   g_xph);
    cudaGetSymbolAddress((void**)&xpl,   g_xpl);
    cudaGetSymbolAddress((void**)&xdh,   g_xdh);
    cudaGetSymbolAddress((void**)&xdl,   g_xdl);
    cudaGetSymbolAddress((void**)&pred,  g_pred);
    cudaGetSymbolAddress((void**)&y0h,   g_y0h);
    cudaGetSymbolAddress((void**)&y0l,   g_y0l);
    cudaGetSymbolAddress((void**)&zb,    g_zb);
    cudaGetSymbolAddress((void**)&c0,    g_c0);
    cudaGetSymbolAddress((void**)&c1,    g_c1);
    cudaGetSymbolAddress((void**)&h1h,   g_h1h);
    cudaGetSymbolAddress((void**)&h1l,   g_h1l);
    cudaGetSymbolAddress((void**)&h0h,   g_h0h);
    cudaGetSymbolAddress((void**)&h0l,   g_h0l);
    cudaGetSymbolAddress((void**)&h1f,   g_h1f);
    cudaGetSymbolAddress((void**)&h0f,   g_h0f);
    cudaGetSymbolAddress((void**)&w0h,   g_w0h);
    cudaGetSymbolAddress((void**)&w0l,   g_w0l);
    cudaGetSymbolAddress((void**)&w1hhh, g_w1hh_h);
    cudaGetSymbolAddress((void**)&w1hhl, g_w1hh_l);
    cudaGetSymbolAddress((void**)&w1ihh, g_w1ih_h);
    cudaGetSymbolAddress((void**)&w1ihl, g_w1ih_l);
    cudaGetSymbolAddress((void**)&wx0h,  g_wx0h);
    cudaGetSymbolAddress((void**)&wx0l,  g_wx0l);
    cudaGetSymbolAddress((void**)&br0,   g_br0);
    cudaGetSymbolAddress((void**)&br1,   g_br1);

    cudaFuncSetAttribute(cell_mma, cudaFuncAttributeMaxDynamicSharedMemorySize,
                         SMEM_TOTAL_(32));
    cudaFuncSetAttribute(enc_step, cudaFuncAttributeMaxDynamicSharedMemorySize,
                         SMEM_TOTAL_(32));

    dim3 grid1(8, 32), grid2(8, 64), blk(NTHREADS);

    prep_kernel<<<T_HIST, NB>>>(veg, wh, wf, xph, xpl, xdh, xdl, pred);
    wprep_kernel<<<GROW, 128>>>(Wih0, Whh0, b0, Wih1, Whh1, b1,
                                w0h, w0l, w1hhh, w1hhl, w1ihh, w1ihl,
                                wx0h, wx0l, br0, br1);
    zero_kernel<<<(HB + 255) / 256, 256>>>(c0, c1, zb);

    // L0(0) alone
    cell_mma<<<grid1, blk, SMEM_TOTAL_(32)>>>(
        zb, zb, w0h, w0l, xph, xpl, wx0h, wx0l,
        1, XPW, br0, c0, h0f, y0h, y0l);

    // merged wavefront: t = 0..148 computes L1(t) and L0(t+1) concurrently
    for (int t = 0; t < T_HIST - 1; t++) {
        const __nv_bfloat16* h1pH = (t == 0) ? zb : (h1h + ((t + 1) & 1) * HB);
        const __nv_bfloat16* h1pL = (t == 0) ? zb : (h1l + ((t + 1) & 1) * HB);
        enc_step<<<grid2, blk, SMEM_TOTAL_(32)>>>(
            h1pH, h1pL, w1hhh, w1hhl,
            y0h + (size_t)t * HB, y0l + (size_t)t * HB, w1ihh, w1ihl,
            br1, c1, h1f, h1h + (t & 1) * HB, h1l + (t & 1) * HB,
            xph + (size_t)(t + 1) * NB * XPW, xpl + (size_t)(t + 1) * NB * XPW,
            w0h, w0l, wx0h, wx0l,
            br0, c0, h0f,
            y0h + (size_t)(t + 1) * HB, y0l + (size_t)(t + 1) * HB);
    }
    // final L1(149): reads h1[148&1=0], writes h1[149&1=1]
    {
        int t = T_HIST - 1;
        cell_mma<<<grid1, blk, SMEM_TOTAL_(32)>>>(
            h1h + ((t + 1) & 1) * HB, h1l + ((t + 1) & 1) * HB, w1hhh, w1hhl,
            y0h + (size_t)t * HB, y0l + (size_t)t * HB, w1ihh, w1ihl,
            8, HID, br1, c1, h1f, h1h + (t & 1) * HB, h1l + (t & 1) * HB);
    }

    // decoder (serial dependence); h1 phases: read (t+1)&1, write t&1
    for (int t = 0; t < T_FUT; t++) {
        const __nv_bfloat16* hpH = (t == 0) ? (y0h + (size_t)(T_HIST - 1) * HB)
                                            : (h0h + ((t + 1) & 1) * HB);
        const __nv_bfloat16* hpL = (t == 0) ? (y0l + (size_t)(T_HIST - 1) * HB)
                                            : (h0l + ((t + 1) & 1) * HB);
        cell_mma<<<grid1, blk, SMEM_TOTAL_(32)>>>(
            hpH, hpL, w0h, w0l, xdh, xdl, wx0h, wx0l,
            1, XPW, br0, c0, h0f, h0h + (t & 1) * HB, h0l + (t & 1) * HB);
        cell_mma<<<grid1, blk, SMEM_TOTAL_(32)>>>(
            h1h + ((t + 1) & 1) * HB, h1l + ((t + 1) & 1) * HB, w1hhh, w1hhl,
            h0h + (t & 1) * HB, h0l + (t & 1) * HB, w1ihh, w1ihl,
            8, HID, br1, c1, h1f, h1h + (t & 1) * HB, h1l + (t & 1) * HB);
        const float* wfn = (t < T_FUT - 1) ? (wf + (t + 1) * WEA) : nullptr;
        head_kernel<<<NB, 128>>>(h1f, headW, headb, pred,
                                 out + t * VEG, wfn, xdh, xdl);
    }
}

// round 13
// speedup vs baseline: 2.7204x; 1.3673x over previous
#include <cuda_runtime.h>
#include <cuda_fp16.h>
#include <cstdint>
#include <math.h>

// ---------------------------------------------------------------------------
// Problem constants
// ---------------------------------------------------------------------------
#define VEG 4
#define WEA 8
#define HID 512
#define NB  256
#define T_HIST 150
#define T_FUT  50
#define HB (NB * HID)
#define XPW 64            // padded x width (12 real + 52 zeros)
#define GROW 2048         // gate rows (4*HID)
#define NTHREADS 256      // 8 warps per CTA, occupancy 2

// ---------------------------------------------------------------------------
// Device scratch (static only) — fp16 activations, fp16 hi/lo weights
// ---------------------------------------------------------------------------
__device__ __half g_xp[T_HIST * NB * XPW];
__device__ __half g_xd[NB * XPW];
__device__ float g_pred[NB * VEG];
__device__ __half g_y0[T_HIST * HB];     // layer0 outputs (h-chain)
__device__ __half g_zb[HB];              // fp16 zeros
__device__ float g_c0[HB];
__device__ float g_c1[HB];
__device__ __half g_h1[2 * HB];
__device__ __half g_h0[2 * HB];
__device__ float g_h1f[HB];
__device__ float g_h0f[HB];              // sink for layer0 fp32 h
// reordered (row = u*4+g) fp16 hi/lo weight splits
__device__ __half g_w0h[GROW * HID], g_w0l[GROW * HID];        // Whh0
__device__ __half g_w1hh_h[GROW * HID], g_w1hh_l[GROW * HID];  // Whh1
__device__ __half g_w1ih_h[GROW * HID], g_w1ih_l[GROW * HID];  // Wih1
__device__ __half g_wx0h[GROW * XPW], g_wx0l[GROW * XPW];      // Wih0 padded
__device__ float g_br0[GROW], g_br1[GROW];

// ---------------------------------------------------------------------------
// Portable PTX helpers (sm_80+ only)
// ---------------------------------------------------------------------------
__device__ __forceinline__ uint32_t smem_u32(const void* p) {
    uint32_t a;
    asm("{ .reg .u64 t; cvta.to.shared.u64 t, %1; cvt.u32.u64 %0, t; }"
        : "=r"(a) : "l"(p));
    return a;
}
#define CP_ASYNC16(dst, src) \
    asm volatile("cp.async.cg.shared.global [%0], [%1], 16;" \
                 :: "r"(dst), "l"(src) : "memory")
#define CP_COMMIT() asm volatile("cp.async.commit_group;" ::: "memory")
#define CP_WAIT1()  asm volatile("cp.async.wait_group 1;" ::: "memory")
#define CP_WAIT0()  asm volatile("cp.async.wait_group 0;" ::: "memory")

#define LDM4(r, addr) \
    asm volatile("ldmatrix.sync.aligned.m8n8.x4.shared.b16 {%0,%1,%2,%3}, [%4];" \
                 : "=r"((r)[0]), "=r"((r)[1]), "=r"((r)[2]), "=r"((r)[3]) \
                 : "r"(addr))

#define MMA16816F(d, a, b0, b1) \
    asm volatile( \
        "mma.sync.aligned.m16n8k16.row.col.f32.f16.f16.f32 " \
        "{%0,%1,%2,%3}, {%4,%5,%6,%7}, {%8,%9}, {%0,%1,%2,%3};" \
        : "+f"((d)[0]), "+f"((d)[1]), "+f"((d)[2]), "+f"((d)[3]) \
        : "r"((a)[0]), "r"((a)[1]), "r"((a)[2]), "r"((a)[3]), \
          "r"(b0), "r"(b1))

// ---------------------------------------------------------------------------
// SMEM layout: A single + B hi/lo, 3 stages
// ---------------------------------------------------------------------------
#define SM_STRIDE 72                        // fp16 elems/row (144B, conflict-free)
#define ROW_B (SM_STRIDE * 2)               // 144 bytes
#define B_TILE_BYTES (64 * ROW_B)           // 9216
#define NSTAGE 3
#define CS_STRIDE 68                        // fp32 C tile row stride

#define A_TILE_BYTES_(MT) ((MT) * ROW_B)
#define STAGE_BYTES_(MT)  (A_TILE_BYTES_(MT) + 2 * B_TILE_BYTES)
#define OFF_BIAS_(MT)     (NSTAGE * STAGE_BYTES_(MT))
#define SMEM_TOTAL_(MT)   (OFF_BIAS_(MT) + 64 * 4 + 16)
// MT=32: stage 23040, total 69392 (2/SM = 139KB)
// MT=64: stage 27648, total 83216 (2/SM = 166KB)

// ---------------------------------------------------------------------------
// Math helpers
// ---------------------------------------------------------------------------
__device__ __forceinline__ float sigmoidf_(float x) { return 1.0f / (1.0f + __expf(-x)); }
__device__ __forceinline__ float tanhf_(float x)    { return 2.0f / (1.0f + __expf(-2.0f * x)) - 1.0f; }
__device__ __forceinline__ void wsplit(float x, __half& h, __half& l) {
    h = __float2half(x);
    l = __float2half(x - __half2float(h));
}

// ---------------------------------------------------------------------------
// prep: smoothing + padded-x fp16 for encoder; decoder init at t=149
// ---------------------------------------------------------------------------
__global__ void prep_kernel(const float* __restrict__ veg,
                            const float* __restrict__ wh,
                            const float* __restrict__ wf,
                            __half* __restrict__ xp,
                            __half* __restrict__ xd,
                            float* __restrict__ pred) {
    int b = threadIdx.x;
    int t = blockIdx.x;
    const int base = (t * NB + b) * XPW;
    float vs[VEG];
#pragma unroll
    for (int v = 0; v < VEG; v++) {
        float val = veg[b * (T_HIST * VEG) + t * VEG + v];
        float s = 0.f;
#pragma unroll
        for (int dt = -2; dt <= 2; dt++) {
            int tt = t + dt;
            if (tt >= 0 && tt < T_HIST) {
                float u = veg[b * (T_HIST * VEG) + tt * VEG + v];
                if (!isnan(u)) s += u;
            }
        }
        float sm = s * 0.2f;
        float outv = isnan(val) ? sm : val;
        if (isnan(outv)) outv = 0.f;
        vs[v] = outv;
        xp[base + v] = __float2half(outv);
    }
#pragma unroll
    for (int k = 0; k < WEA; k++)
        xp[base + VEG + k] = __float2half(wh[b * (T_HIST * WEA) + t * WEA + k]);
    __half z = __float2half(0.f);
    for (int c = VEG + WEA; c < XPW; c++) xp[base + c] = z;

    if (t == T_HIST - 1) {
        int db = b * XPW;
#pragma unroll
        for (int v = 0; v < VEG; v++) {
            pred[b * VEG + v] = vs[v];
            xd[db + v] = __float2half(vs[v]);
        }
#pragma unroll
        for (int k = 0; k < WEA; k++)
            xd[db + VEG + k] = __float2half(wf[b * (T_FUT * WEA) + k]);
        for (int c = VEG + WEA; c < XPW; c++) xd[db + c] = z;
    }
}

// ---------------------------------------------------------------------------
// weight prep: reorder rows to u*4+g, fp16 hi/lo split, pad Wih0 to 64 cols
// ---------------------------------------------------------------------------
__global__ void wprep_kernel(const float* __restrict__ Wih0, const float* __restrict__ Whh0,
                             const float* __restrict__ b0,   const float* __restrict__ Wih1,
                             const float* __restrict__ Whh1, const float* __restrict__ b1,
                             __half* w0h, __half* w0l,
                             __half* w1hhh, __half* w1hhl,
                             __half* w1ihh, __half* w1ihl,
                             __half* wx0h, __half* wx0l,
                             float* br0, float* br1) {
    int rn = blockIdx.x;                       // new row
    int orig = (rn & 3) * HID + (rn >> 2);     // g*512 + u
    for (int c = threadIdx.x; c < HID; c += blockDim.x) {
        __half hh, ll;
        wsplit(Whh0[orig * HID + c], hh, ll);
        w0h[rn * HID + c] = hh; w0l[rn * HID + c] = ll;
        wsplit(Whh1[orig * HID + c], hh, ll);
        w1hhh[rn * HID + c] = hh; w1hhl[rn * HID + c] = ll;
        wsplit(Wih1[orig * HID + c], hh, ll);
        w1ihh[rn * HID + c] = hh; w1ihl[rn * HID + c] = ll;
    }
    if (threadIdx.x < XPW) {
        int c = threadIdx.x;
        float v = (c < VEG + WEA) ? Wih0[orig * (VEG + WEA) + c] : 0.f;
        __half hh, ll; wsplit(v, hh, ll);
        wx0h[rn * XPW + c] = hh; wx0l[rn * XPW + c] = ll;
    }
    if (threadIdx.x == 0) { br0[rn] = b0[orig]; br1[rn] = b1[orig]; }
}

__global__ void zero_kernel(float* __restrict__ c0, float* __restrict__ c1,
                            __half* __restrict__ zb) {
    int i = blockIdx.x * blockDim.x + threadIdx.x;
    if (i < HB) { c0[i] = 0.f; c1[i] = 0.f; zb[i] = __float2half(0.f); }
}

// ---------------------------------------------------------------------------
// Cell body: one MT(batch)x64(gate) tile of a fused LSTM step on fp16 HMMA.
// Activations single fp16, weights 2-pass hi/lo fp16 split (error ~2e-4).
// 8 warps: (MT/32) M x 2 N x KS K-groups, warp tile 32x32.
// 3-stage cp.async pipeline, per-K-group C slabs summed in the epilogue.
// ---------------------------------------------------------------------------
template <int MT>
__device__ __forceinline__ void cell_body(
    char* smem, int m0, int tileY,
    const __half* __restrict__ Ah,                                  // h (single)
    const __half* __restrict__ BhH, const __half* __restrict__ BhL, // Whh hi/lo
    const __half* __restrict__ Ax,                                  // x (single)
    const __half* __restrict__ BxH, const __half* __restrict__ BxL, // Wx hi/lo
    int ncx, int ldx,
    const float* __restrict__ biasr,
    float* __restrict__ c, float* __restrict__ hf,
    __half* __restrict__ hout) {

    constexpr int A_TILE = A_TILE_BYTES_(MT);
    constexpr int STAGE  = STAGE_BYTES_(MT);
    constexpr int OFF_A  = 0;
    constexpr int OFF_BH = A_TILE;
    constexpr int OFF_BL = A_TILE + B_TILE_BYTES;
    constexpr int OFF_BIAS = OFF_BIAS_(MT);
    constexpr int WM = MT / 32;           // M warp-slices (1 or 2)
    constexpr int KS = 8 / (WM * 2);      // K-groups (4 or 2)
    constexpr int KITER = 4 / KS;         // kk slices per warp per chunk
    constexpr int CSLAB = MT * CS_STRIDE; // floats per K-group C slab
    static_assert(WM * 2 * KS == 8, "warp layout");

    const uint32_t sbase = smem_u32(smem);
    const int tid = threadIdx.x;
    const int warp = tid >> 5;
    const int lane = tid & 31;
    const int n0 = tileY * 64;            // reordered weight row base
    const int u0 = tileY * 16;            // unit base
    const int ks = warp % KS;
    const int rem = warp / KS;
    const int wn = rem & 1;               // 0..1 (32-col slices)
    const int wm = rem >> 1;              // 0..WM-1 (32-row slices)

    if (tid < 64)
        *reinterpret_cast<float*>(smem + OFF_BIAS + tid * 4) = biasr[n0 + tid];

    float cfr[2][4][4];   // A * W_hi
    float cfl[2][4][4];   // A * W_lo
#pragma unroll
    for (int mi = 0; mi < 2; mi++)
#pragma unroll
        for (int nj = 0; nj < 4; nj++)
#pragma unroll
            for (int r = 0; r < 4; r++) { cfr[mi][nj][r] = 0.f; cfl[mi][nj][r] = 0.f; }

    const int NC = 8 + ncx;

    auto prefetch = [&](int ch) {
        const __half *aP, *bH, *bL;
        int lda, k0;
        if (ch < 8) { aP = Ah; bH = BhH; bL = BhL; lda = HID; k0 = ch * 64; }
        else        { aP = Ax; bH = BxH; bL = BxL; lda = ldx; k0 = (ch - 8) * 64; }
        const uint32_t st = sbase + (ch % NSTAGE) * STAGE;
        // A: MT rows x 64 fp16 (MT*8 16B chunks), single
#pragma unroll
        for (int i = 0; i < (MT * 8) / NTHREADS; i++) {
            int idx = tid + i * NTHREADS;
            int r = idx >> 3, q = idx & 7;
            uint32_t off = r * ROW_B + q * 16;
            long ao = (long)(m0 + r) * lda + k0 + q * 8;
            CP_ASYNC16(st + OFF_A + off, aP + ao);
        }
        // B: 64 rows x 64 fp16 (512 16B chunks), hi + lo
#pragma unroll
        for (int i = 0; i < 512 / NTHREADS; i++) {
            int idx = tid + i * NTHREADS;
            int r = idx >> 3, q = idx & 7;
            uint32_t off = r * ROW_B + q * 16;
            long bo = (long)(n0 + r) * lda + k0 + q * 8;
            CP_ASYNC16(st + OFF_BH + off, bH + bo);
            CP_ASYNC16(st + OFF_BL + off, bL + bo);
        }
    };

    prefetch(0); CP_COMMIT();
    prefetch(1); CP_COMMIT();

    for (int ch = 0; ch < NC; ch++) {
        if (ch + 1 < NC) CP_WAIT1(); else CP_WAIT0();
        __syncthreads();                    // publishes chunk ch
        if (ch + 2 < NC) { prefetch(ch + 2); CP_COMMIT(); }

        const uint32_t base = sbase + (ch % NSTAGE) * STAGE;
#pragma unroll
        for (int ki = 0; ki < KITER; ki++) {
            const int kk = (ks * KITER + ki) * 16;
            uint32_t ah[2][4], bh[4][2], bl[4][2];
#pragma unroll
            for (int mi = 0; mi < 2; mi++) {
                uint32_t roff =
                    (uint32_t)((wm * 32 + mi * 16 + (lane & 15)) * ROW_B +
                               (kk + (lane >> 4) * 8) * 2);
                LDM4(ah[mi], base + OFF_A + roff);
            }
#pragma unroll
            for (int p = 0; p < 2; p++) {
                uint32_t roff =
                    (uint32_t)((wn * 32 + p * 16 + (lane & 15)) * ROW_B +
                               (kk + (lane >> 4) * 8) * 2);
                uint32_t rb[4], rl[4];
                LDM4(rb, base + OFF_BH + roff);
                LDM4(rl, base + OFF_BL + roff);
                bh[p * 2 + 0][0] = rb[0]; bh[p * 2 + 0][1] = rb[2];
                bh[p * 2 + 1][0] = rb[1]; bh[p * 2 + 1][1] = rb[3];
                bl[p * 2 + 0][0] = rl[0]; bl[p * 2 + 0][1] = rl[2];
                bl[p * 2 + 1][0] = rl[1]; bl[p * 2 + 1][1] = rl[3];
            }
#pragma unroll
            for (int mi = 0; mi < 2; mi++)
#pragma unroll
                for (int nj = 0; nj < 4; nj++) {
                    MMA16816F(cfr[mi][nj], ah[mi], bh[nj][0], bh[nj][1]);
                    MMA16816F(cfl[mi][nj], ah[mi], bl[nj][0], bl[nj][1]);
                }
        }
    }
    __syncthreads();   // all ldmatrix reads done before Cs overwrites stage 0

    // ---- epilogue: per-K-group C slabs (single barrier) ----
    float* Cs = reinterpret_cast<float*>(smem);   // KS slabs of MT x CS_STRIDE
    {
        float* Cg = Cs + ks * CSLAB;
#pragma unroll
        for (int mi = 0; mi < 2; mi++)
#pragma unroll
            for (int nj = 0; nj < 4; nj++) {
                int r = wm * 32 + mi * 16 + (lane >> 2);
                int col = wn * 32 + nj * 8 + (lane & 3) * 2;
                Cg[r * CS_STRIDE + col]           = cfr[mi][nj][0] + cfl[mi][nj][0];
                Cg[r * CS_STRIDE + col + 1]       = cfr[mi][nj][1] + cfl[mi][nj][1];
                Cg[(r + 8) * CS_STRIDE + col]     = cfr[mi][nj][2] + cfl[mi][nj][2];
                Cg[(r + 8) * CS_STRIDE + col + 1] = cfr[mi][nj][3] + cfl[mi][nj][3];
            }
    }
    __syncthreads();

    const float* Bs = reinterpret_cast<const float*>(smem + OFF_BIAS);
#pragma unroll
    for (int k = 0; k < (MT * 16) / NTHREADS; k++) {
        int id = tid + k * NTHREADS;
        int u = id & 15, bb = id >> 4;        // bb 0..MT-1
        float4 g4 = *reinterpret_cast<const float4*>(&Cs[bb * CS_STRIDE + u * 4]);
#pragma unroll
        for (int g = 1; g < (8 / ((MT / 32) * 2)); g++) {
            float4 p4 = *reinterpret_cast<const float4*>(
                &Cs[g * CSLAB + bb * CS_STRIDE + u * 4]);
            g4.x += p4.x; g4.y += p4.y; g4.z += p4.z; g4.w += p4.w;
        }
        float gi = sigmoidf_(g4.x + Bs[u * 4 + 0]);
        float gf = sigmoidf_(g4.y + Bs[u * 4 + 1]);
        float gg = tanhf_   (g4.z + Bs[u * 4 + 2]);
        float go = sigmoidf_(g4.w + Bs[u * 4 + 3]);
        int gidx = (m0 + bb) * HID + u0 + u;
        float cn = gf * c[gidx] + gi * gg;
        c[gidx] = cn;
        float hv = go * tanhf_(cn);
        hf[gidx] = hv;
        hout[gidx] = __float2half(hv);
    }
}

// ---------------------------------------------------------------------------
// Single-cell kernel: MT=32, grid (8,32)=256 CTAs, 2 CTAs/SM resident
// ---------------------------------------------------------------------------
__global__ void __launch_bounds__(NTHREADS, 2)
cell_mma(const __half* __restrict__ Ah,
         const __half* __restrict__ BhH, const __half* __restrict__ BhL,
         const __half* __restrict__ Ax,
         const __half* __restrict__ BxH, const __half* __restrict__ BxL,
         int ncx, int ldx,
         const float* __restrict__ biasr,
         float* __restrict__ c, float* __restrict__ hf,
         __half* __restrict__ hout) {
    extern __shared__ __align__(16) char smem[];
    cell_body<32>(smem, blockIdx.x * 32, blockIdx.y,
                  Ah, BhH, BhL, Ax, BxH, BxL,
                  ncx, ldx, biasr, c, hf, hout);
}

// ---------------------------------------------------------------------------
// Merged encoder wavefront step: MT=64, grid (4,64)=256 CTAs, 2/SM resident.
// L1(t) on tiles y<32, L0(t+1) on tiles y>=32.
// ---------------------------------------------------------------------------
__global__ void __launch_bounds__(NTHREADS, 2)
enc_step(const __half* __restrict__ h1p,
         const __half* __restrict__ w1hhh, const __half* __restrict__ w1hhl,
         const __half* __restrict__ y0t,
         const __half* __restrict__ w1ihh, const __half* __restrict__ w1ihl,
         const float* __restrict__ br1, float* __restrict__ c1,
         float* __restrict__ h1f, __half* __restrict__ h1o,
         const __half* __restrict__ xn,
         const __half* __restrict__ w0h, const __half* __restrict__ w0l,
         const __half* __restrict__ wx0h, const __half* __restrict__ wx0l,
         const float* __restrict__ br0, float* __restrict__ c0,
         float* __restrict__ h0f, __half* __restrict__ y0n) {
    extern __shared__ __align__(16) char smem[];
    const int m0 = blockIdx.x * 64;
    if (blockIdx.y < 32) {
        cell_body<64>(smem, m0, blockIdx.y,
                      h1p, w1hhh, w1hhl, y0t, w1ihh, w1ihl,
                      8, HID, br1, c1, h1f, h1o);
    } else {
        cell_body<64>(smem, m0, blockIdx.y - 32,
                      y0t, w0h, w0l, xn, wx0h, wx0l,
                      1, XPW, br0, c0, h0f, y0n);
    }
}

// ---------------------------------------------------------------------------
// head: pred += h1 @ headW^T + headb ; write output[t]; build next decoder x
// ---------------------------------------------------------------------------
__global__ void head_kernel(const float* __restrict__ h1,
                            const float* __restrict__ headW,
                            const float* __restrict__ headb,
                            float* __restrict__ pred,
                            float* __restrict__ out_t,
                            const float* __restrict__ wf_next,
                            __half* __restrict__ xd) {
    int b = blockIdx.x;
    int w = threadIdx.x >> 5;
    int lane = threadIdx.x & 31;
    const float* hr = &h1[b * HID];
    const float* wr = &headW[w * HID];
    float s = 0.f;
    for (int k = lane; k < HID; k += 32) s += hr[k] * wr[k];
#pragma unroll
    for (int o = 16; o; o >>= 1) s += __shfl_down_sync(0xffffffffu, s, o);
    if (lane == 0) {
        float p = pred[b * VEG + w] + s + headb[w];
        pred[b * VEG + w] = p;
        out_t[b * (T_FUT * VEG) + w] = p;
        xd[b * XPW + w] = __float2half(p);
    }
    if (threadIdx.x < WEA && wf_next)
        xd[b * XPW + VEG + threadIdx.x] =
            __float2half(wf_next[b * (T_FUT * WEA) + threadIdx.x]);
}

// ---------------------------------------------------------------------------
// Host launcher (single stream — graph-capture safe)
// ---------------------------------------------------------------------------
extern "C" void kernel_launch(void* const* d_in, const int* in_sizes, int n_in,
                              void* d_out, int out_size) {
    const float* veg   = (const float*)d_in[0];
    const float* wh    = (const float*)d_in[1];
    const float* wf    = (const float*)d_in[2];
    const float* Wih0  = (const float*)d_in[3];
    const float* Whh0  = (const float*)d_in[4];
    const float* b0    = (const float*)d_in[5];
    const float* Wih1  = (const float*)d_in[6];
    const float* Whh1  = (const float*)d_in[7];
    const float* b1    = (const float*)d_in[8];
    const float* headW = (const float*)d_in[9];
    const float* headb = (const float*)d_in[10];
    float* out = (float*)d_out;

    __half *xp, *xd, *y0, *zb, *h1, *h0;
    __half *w0h, *w0l, *w1hhh, *w1hhl, *w1ihh, *w1ihl, *wx0h, *wx0l;
    float *pred, *c0, *c1, *h1f, *h0f, *br0, *br1;
    cudaGetSymbolAddress((void**)&xp,    g_xp);
    cudaGetSymbolAddress((void**)&xd,    g_xd);
    cudaGetSymbolAddress((void**)&pred,  g_pred);
    cudaGetSymbolAddress((void**)&y0,    g_y0);
    cudaGetSymbolAddress((void**)&zb,    g_zb);
    cudaGetSymbolAddress((void**)&c0,    g_c0);
    cudaGetSymbolAddress((void**)&c1,    g_c1);
    cudaGetSymbolAddress((void**)&h1,    g_h1);
    cudaGetSymbolAddress((void**)&h0,    g_h0);
    cudaGetSymbolAddress((void**)&h1f,   g_h1f);
    cudaGetSymbolAddress((void**)&h0f,   g_h0f);
    cudaGetSymbolAddress((void**)&w0h,   g_w0h);
    cudaGetSymbolAddress((void**)&w0l,   g_w0l);
    cudaGetSymbolAddress((void**)&w1hhh, g_w1hh_h);
    cudaGetSymbolAddress((void**)&w1hhl, g_w1hh_l);
    cudaGetSymbolAddress((void**)&w1ihh, g_w1ih_h);
    cudaGetSymbolAddress((void**)&w1ihl, g_w1ih_l);
    cudaGetSymbolAddress((void**)&wx0h,  g_wx0h);
    cudaGetSymbolAddress((void**)&wx0l,  g_wx0l);
    cudaGetSymbolAddress((void**)&br0,   g_br0);
    cudaGetSymbolAddress((void**)&br1,   g_br1);

    cudaFuncSetAttribute(cell_mma, cudaFuncAttributeMaxDynamicSharedMemorySize,
                         SMEM_TOTAL_(32));
    cudaFuncSetAttribute(enc_step, cudaFuncAttributeMaxDynamicSharedMemorySize,
                         SMEM_TOTAL_(64));

    dim3 grid1(8, 32), grid2(4, 64), blk(NTHREADS);

    prep_kernel<<<T_HIST, NB>>>(veg, wh, wf, xp, xd, pred);
    wprep_kernel<<<GROW, 128>>>(Wih0, Whh0, b0, Wih1, Whh1, b1,
                                w0h, w0l, w1hhh, w1hhl, w1ihh, w1ihl,
                                wx0h, wx0l, br0, br1);
    zero_kernel<<<(HB + 255) / 256, 256>>>(c0, c1, zb);

    // L0(0) alone
    cell_mma<<<grid1, blk, SMEM_TOTAL_(32)>>>(
        zb, w0h, w0l, xp, wx0h, wx0l,
        1, XPW, br0, c0, h0f, y0);

    // merged wavefront: t = 0..148 computes L1(t) and L0(t+1) concurrently
    for (int t = 0; t < T_HIST - 1; t++) {
        const __half* h1p = (t == 0) ? zb : (h1 + ((t + 1) & 1) * HB);
        enc_step<<<grid2, blk, SMEM_TOTAL_(64)>>>(
            h1p, w1hhh, w1hhl,
            y0 + (size_t)t * HB, w1ihh, w1ihl,
            br1, c1, h1f, h1 + (t & 1) * HB,
            xp + (size_t)(t + 1) * NB * XPW,
            w0h, w0l, wx0h, wx0l,
            br0, c0, h0f, y0 + (size_t)(t + 1) * HB);
    }
    // final L1(149): reads h1[148&1=0], writes h1[149&1=1]
    {
        int t = T_HIST - 1;
        cell_mma<<<grid1, blk, SMEM_TOTAL_(32)>>>(
            h1 + ((t + 1) & 1) * HB, w1hhh, w1hhl,
            y0 + (size_t)t * HB, w1ihh, w1ihl,
            8, HID, br1, c1, h1f, h1 + (t & 1) * HB);
    }

    // decoder (serial dependence); h1 phases: read (t+1)&1, write t&1
    for (int t = 0; t < T_FUT; t++) {
        const __half* hp = (t == 0) ? (y0 + (size_t)(T_HIST - 1) * HB)
                                    : (h0 + ((t + 1) & 1) * HB);
        cell_mma<<<grid1, blk, SMEM_TOTAL_(32)>>>(
            hp, w0h, w0l, xd, wx0h, wx0l,
            1, XPW, br0, c0, h0f, h0 + (t & 1) * HB);
        cell_mma<<<grid1, blk, SMEM_TOTAL_(32)>>>(
            h1 + ((t + 1) & 1) * HB, w1hhh, w1hhl,
            h0 + (t & 1) * HB, w1ihh, w1ihl,
            8, HID, br1, c1, h1f, h1 + (t & 1) * HB);
        const float* wfn = (t < T_FUT - 1) ? (wf + (t + 1) * WEA) : nullptr;
        head_kernel<<<NB, 128>>>(h1f, headW, headb, pred,
                                 out + t * VEG, wfn, xd);
    }
}

// round 14
// speedup vs baseline: 3.9783x; 1.4624x over previous
#include <cuda_runtime.h>
#include <cuda_fp16.h>
#include <cstdint>
#include <math.h>

// ---------------------------------------------------------------------------
// Problem constants
// ---------------------------------------------------------------------------
#define VEG 4
#define WEA 8
#define HID 512
#define NB  256
#define T_HIST 150
#define T_FUT  50
#define HB (NB * HID)
#define XPW 64            // padded x width (12 real + 52 zeros)
#define GROW 2048         // gate rows (4*HID)
#define NTHREADS 256      // 8 warps per CTA, occupancy 2

// ---------------------------------------------------------------------------
// Device scratch (static only) — pure fp16 activations and weights
// ---------------------------------------------------------------------------
__device__ __half g_xp[T_HIST * NB * XPW];
__device__ __half g_xd[NB * XPW];
__device__ float g_pred[NB * VEG];
__device__ __half g_y0[T_HIST * HB];     // layer0 outputs (h-chain)
__device__ __half g_zb[HB];              // fp16 zeros
__device__ float g_c0[HB];
__device__ float g_c1[HB];
__device__ __half g_h1[2 * HB];
__device__ __half g_h0[2 * HB];
__device__ float g_h1f[HB];
__device__ float g_h0f[HB];              // sink for layer0 fp32 h
// reordered (row = u*4+g) fp16 weights
__device__ __half g_w0[GROW * HID];      // Whh0
__device__ __half g_w1hh[GROW * HID];    // Whh1
__device__ __half g_w1ih[GROW * HID];    // Wih1
__device__ __half g_wx0[GROW * XPW];     // Wih0 padded
__device__ float g_br0[GROW], g_br1[GROW];

// ---------------------------------------------------------------------------
// Portable PTX helpers (sm_80+ only)
// ---------------------------------------------------------------------------
__device__ __forceinline__ uint32_t smem_u32(const void* p) {
    uint32_t a;
    asm("{ .reg .u64 t; cvta.to.shared.u64 t, %1; cvt.u32.u64 %0, t; }"
        : "=r"(a) : "l"(p));
    return a;
}
#define CP_ASYNC16(dst, src) \
    asm volatile("cp.async.cg.shared.global [%0], [%1], 16;" \
                 :: "r"(dst), "l"(src) : "memory")
#define CP_COMMIT() asm volatile("cp.async.commit_group;" ::: "memory")
#define CP_WAIT1()  asm volatile("cp.async.wait_group 1;" ::: "memory")
#define CP_WAIT0()  asm volatile("cp.async.wait_group 0;" ::: "memory")

#define LDM4(r, addr) \
    asm volatile("ldmatrix.sync.aligned.m8n8.x4.shared.b16 {%0,%1,%2,%3}, [%4];" \
                 : "=r"((r)[0]), "=r"((r)[1]), "=r"((r)[2]), "=r"((r)[3]) \
                 : "r"(addr))

#define MMA16816F(d, a, b0, b1) \
    asm volatile( \
        "mma.sync.aligned.m16n8k16.row.col.f32.f16.f16.f32 " \
        "{%0,%1,%2,%3}, {%4,%5,%6,%7}, {%8,%9}, {%0,%1,%2,%3};" \
        : "+f"((d)[0]), "+f"((d)[1]), "+f"((d)[2]), "+f"((d)[3]) \
        : "r"((a)[0]), "r"((a)[1]), "r"((a)[2]), "r"((a)[3]), \
          "r"(b0), "r"(b1))

// ---------------------------------------------------------------------------
// SMEM layout: A + B (single precision each), 3 stages
// ---------------------------------------------------------------------------
#define SM_STRIDE 72                        // fp16 elems/row (144B, conflict-free)
#define ROW_B (SM_STRIDE * 2)               // 144 bytes
#define B_TILE_BYTES (64 * ROW_B)           // 9216
#define NSTAGE 3
#define CS_STRIDE 68                        // fp32 C tile row stride

#define A_TILE_BYTES_(MT) ((MT) * ROW_B)
#define STAGE_BYTES_(MT)  (A_TILE_BYTES_(MT) + B_TILE_BYTES)
#define OFF_BIAS_(MT)     (NSTAGE * STAGE_BYTES_(MT))
#define SMEM_TOTAL_(MT)   (OFF_BIAS_(MT) + 64 * 4 + 16)
// MT=32: stage 13824, total 41744.  MT=64: stage 18432, total 55568.

// ---------------------------------------------------------------------------
// Math helpers
// ---------------------------------------------------------------------------
__device__ __forceinline__ float sigmoidf_(float x) { return 1.0f / (1.0f + __expf(-x)); }
__device__ __forceinline__ float tanhf_(float x)    { return 2.0f / (1.0f + __expf(-2.0f * x)) - 1.0f; }

// ---------------------------------------------------------------------------
// prep: smoothing + padded-x fp16 for encoder; decoder init at t=149
// ---------------------------------------------------------------------------
__global__ void prep_kernel(const float* __restrict__ veg,
                            const float* __restrict__ wh,
                            const float* __restrict__ wf,
                            __half* __restrict__ xp,
                            __half* __restrict__ xd,
                            float* __restrict__ pred) {
    int b = threadIdx.x;
    int t = blockIdx.x;
    const int base = (t * NB + b) * XPW;
    float vs[VEG];
#pragma unroll
    for (int v = 0; v < VEG; v++) {
        float val = veg[b * (T_HIST * VEG) + t * VEG + v];
        float s = 0.f;
#pragma unroll
        for (int dt = -2; dt <= 2; dt++) {
            int tt = t + dt;
            if (tt >= 0 && tt < T_HIST) {
                float u = veg[b * (T_HIST * VEG) + tt * VEG + v];
                if (!isnan(u)) s += u;
            }
        }
        float sm = s * 0.2f;
        float outv = isnan(val) ? sm : val;
        if (isnan(outv)) outv = 0.f;
        vs[v] = outv;
        xp[base + v] = __float2half(outv);
    }
#pragma unroll
    for (int k = 0; k < WEA; k++)
        xp[base + VEG + k] = __float2half(wh[b * (T_HIST * WEA) + t * WEA + k]);
    __half z = __float2half(0.f);
    for (int c = VEG + WEA; c < XPW; c++) xp[base + c] = z;

    if (t == T_HIST - 1) {
        int db = b * XPW;
#pragma unroll
        for (int v = 0; v < VEG; v++) {
            pred[b * VEG + v] = vs[v];
            xd[db + v] = __float2half(vs[v]);
        }
#pragma unroll
        for (int k = 0; k < WEA; k++)
            xd[db + VEG + k] = __float2half(wf[b * (T_FUT * WEA) + k]);
        for (int c = VEG + WEA; c < XPW; c++) xd[db + c] = z;
    }
}

// ---------------------------------------------------------------------------
// weight prep: reorder rows to u*4+g, fp16, pad Wih0 to 64 cols
// ---------------------------------------------------------------------------
__global__ void wprep_kernel(const float* __restrict__ Wih0, const float* __restrict__ Whh0,
                             const float* __restrict__ b0,   const float* __restrict__ Wih1,
                             const float* __restrict__ Whh1, const float* __restrict__ b1,
                             __half* w0, __half* w1hh, __half* w1ih, __half* wx0,
                             float* br0, float* br1) {
    int rn = blockIdx.x;                       // new row
    int orig = (rn & 3) * HID + (rn >> 2);     // g*512 + u
    for (int c = threadIdx.x; c < HID; c += blockDim.x) {
        w0[rn * HID + c]   = __float2half(Whh0[orig * HID + c]);
        w1hh[rn * HID + c] = __float2half(Whh1[orig * HID + c]);
        w1ih[rn * HID + c] = __float2half(Wih1[orig * HID + c]);
    }
    if (threadIdx.x < XPW) {
        int c = threadIdx.x;
        float v = (c < VEG + WEA) ? Wih0[orig * (VEG + WEA) + c] : 0.f;
        wx0[rn * XPW + c] = __float2half(v);
    }
    if (threadIdx.x == 0) { br0[rn] = b0[orig]; br1[rn] = b1[orig]; }
}

__global__ void zero_kernel(float* __restrict__ c0, float* __restrict__ c1,
                            __half* __restrict__ zb) {
    int i = blockIdx.x * blockDim.x + threadIdx.x;
    if (i < HB) { c0[i] = 0.f; c1[i] = 0.f; zb[i] = __float2half(0.f); }
}

// ---------------------------------------------------------------------------
// Cell body: one MT(batch)x64(gate) tile of a fused LSTM step on fp16 HMMA.
// Single-pass pure fp16 (error ~1e-4, threshold 1e-3).
// 8 warps: (MT/32) M x 2 N x KS K-groups, warp tile 32x32.
// 3-stage cp.async pipeline, per-K-group C slabs summed in the epilogue.
// ---------------------------------------------------------------------------
template <int MT>
__device__ __forceinline__ void cell_body(
    char* smem, int m0, int tileY,
    const __half* __restrict__ Ah, const __half* __restrict__ Bh,   // h, Whh
    const __half* __restrict__ Ax, const __half* __restrict__ Bx,   // x, Wx
    int ncx, int ldx,
    const float* __restrict__ biasr,
    float* __restrict__ c, float* __restrict__ hf,
    __half* __restrict__ hout) {

    constexpr int A_TILE = A_TILE_BYTES_(MT);
    constexpr int STAGE  = STAGE_BYTES_(MT);
    constexpr int OFF_A  = 0;
    constexpr int OFF_B  = A_TILE;
    constexpr int OFF_BIAS = OFF_BIAS_(MT);
    constexpr int WM = MT / 32;           // M warp-slices (1 or 2)
    constexpr int KS = 8 / (WM * 2);      // K-groups (4 or 2)
    constexpr int KITER = 4 / KS;         // kk slices per warp per chunk
    constexpr int CSLAB = MT * CS_STRIDE; // floats per K-group C slab
    static_assert(WM * 2 * KS == 8, "warp layout");

    const uint32_t sbase = smem_u32(smem);
    const int tid = threadIdx.x;
    const int warp = tid >> 5;
    const int lane = tid & 31;
    const int n0 = tileY * 64;            // reordered weight row base
    const int u0 = tileY * 16;            // unit base
    const int ks = warp % KS;
    const int rem = warp / KS;
    const int wn = rem & 1;               // 0..1 (32-col slices)
    const int wm = rem >> 1;              // 0..WM-1 (32-row slices)

    if (tid < 64)
        *reinterpret_cast<float*>(smem + OFF_BIAS + tid * 4) = biasr[n0 + tid];

    float cf[2][4][4];
#pragma unroll
    for (int mi = 0; mi < 2; mi++)
#pragma unroll
        for (int nj = 0; nj < 4; nj++)
#pragma unroll
            for (int r = 0; r < 4; r++) cf[mi][nj][r] = 0.f;

    const int NC = 8 + ncx;

    auto prefetch = [&](int ch) {
        const __half *aP, *bP;
        int lda, k0;
        if (ch < 8) { aP = Ah; bP = Bh; lda = HID; k0 = ch * 64; }
        else        { aP = Ax; bP = Bx; lda = ldx; k0 = (ch - 8) * 64; }
        const uint32_t st = sbase + (ch % NSTAGE) * STAGE;
        // A: MT rows x 64 fp16 (MT*8 16B chunks)
#pragma unroll
        for (int i = 0; i < (MT * 8) / NTHREADS; i++) {
            int idx = tid + i * NTHREADS;
            int r = idx >> 3, q = idx & 7;
            uint32_t off = r * ROW_B + q * 16;
            long ao = (long)(m0 + r) * lda + k0 + q * 8;
            CP_ASYNC16(st + OFF_A + off, aP + ao);
        }
        // B: 64 rows x 64 fp16 (512 16B chunks)
#pragma unroll
        for (int i = 0; i < 512 / NTHREADS; i++) {
            int idx = tid + i * NTHREADS;
            int r = idx >> 3, q = idx & 7;
            uint32_t off = r * ROW_B + q * 16;
            long bo = (long)(n0 + r) * lda + k0 + q * 8;
            CP_ASYNC16(st + OFF_B + off, bP + bo);
        }
    };

    prefetch(0); CP_COMMIT();
    prefetch(1); CP_COMMIT();

    for (int ch = 0; ch < NC; ch++) {
        if (ch + 1 < NC) CP_WAIT1(); else CP_WAIT0();
        __syncthreads();                    // publishes chunk ch
        if (ch + 2 < NC) { prefetch(ch + 2); CP_COMMIT(); }

        const uint32_t base = sbase + (ch % NSTAGE) * STAGE;
#pragma unroll
        for (int ki = 0; ki < KITER; ki++) {
            const int kk = (ks * KITER + ki) * 16;
            uint32_t ah[2][4], bh[4][2];
#pragma unroll
            for (int mi = 0; mi < 2; mi++) {
                uint32_t roff =
                    (uint32_t)((wm * 32 + mi * 16 + (lane & 15)) * ROW_B +
                               (kk + (lane >> 4) * 8) * 2);
                LDM4(ah[mi], base + OFF_A + roff);
            }
#pragma unroll
            for (int p = 0; p < 2; p++) {
                uint32_t roff =
                    (uint32_t)((wn * 32 + p * 16 + (lane & 15)) * ROW_B +
                               (kk + (lane >> 4) * 8) * 2);
                uint32_t rb[4];
                LDM4(rb, base + OFF_B + roff);
                bh[p * 2 + 0][0] = rb[0]; bh[p * 2 + 0][1] = rb[2];
                bh[p * 2 + 1][0] = rb[1]; bh[p * 2 + 1][1] = rb[3];
            }
#pragma unroll
            for (int mi = 0; mi < 2; mi++)
#pragma unroll
                for (int nj = 0; nj < 4; nj++)
                    MMA16816F(cf[mi][nj], ah[mi], bh[nj][0], bh[nj][1]);
        }
    }
    __syncthreads();   // all ldmatrix reads done before Cs overwrites stage 0

    // ---- epilogue: per-K-group C slabs (single barrier) ----
    float* Cs = reinterpret_cast<float*>(smem);   // KS slabs of MT x CS_STRIDE
    {
        float* Cg = Cs + ks * CSLAB;
#pragma unroll
        for (int mi = 0; mi < 2; mi++)
#pragma unroll
            for (int nj = 0; nj < 4; nj++) {
                int r = wm * 32 + mi * 16 + (lane >> 2);
                int col = wn * 32 + nj * 8 + (lane & 3) * 2;
                Cg[r * CS_STRIDE + col]           = cf[mi][nj][0];
                Cg[r * CS_STRIDE + col + 1]       = cf[mi][nj][1];
                Cg[(r + 8) * CS_STRIDE + col]     = cf[mi][nj][2];
                Cg[(r + 8) * CS_STRIDE + col + 1] = cf[mi][nj][3];
            }
    }
    __syncthreads();

    const float* Bs = reinterpret_cast<const float*>(smem + OFF_BIAS);
#pragma unroll
    for (int k = 0; k < (MT * 16) / NTHREADS; k++) {
        int id = tid + k * NTHREADS;
        int u = id & 15, bb = id >> 4;        // bb 0..MT-1
        float4 g4 = *reinterpret_cast<const float4*>(&Cs[bb * CS_STRIDE + u * 4]);
#pragma unroll
        for (int g = 1; g < (8 / ((MT / 32) * 2)); g++) {
            float4 p4 = *reinterpret_cast<const float4*>(
                &Cs[g * CSLAB + bb * CS_STRIDE + u * 4]);
            g4.x += p4.x; g4.y += p4.y; g4.z += p4.z; g4.w += p4.w;
        }
        float gi = sigmoidf_(g4.x + Bs[u * 4 + 0]);
        float gf = sigmoidf_(g4.y + Bs[u * 4 + 1]);
        float gg = tanhf_   (g4.z + Bs[u * 4 + 2]);
        float go = sigmoidf_(g4.w + Bs[u * 4 + 3]);
        int gidx = (m0 + bb) * HID + u0 + u;
        float cn = gf * c[gidx] + gi * gg;
        c[gidx] = cn;
        float hv = go * tanhf_(cn);
        hf[gidx] = hv;
        hout[gidx] = __float2half(hv);
    }
}

// ---------------------------------------------------------------------------
// Single-cell kernel: MT=32, grid (8,32)=256 CTAs, 2 CTAs/SM resident
// ---------------------------------------------------------------------------
__global__ void __launch_bounds__(NTHREADS, 2)
cell_mma(const __half* __restrict__ Ah, const __half* __restrict__ Bh,
         const __half* __restrict__ Ax, const __half* __restrict__ Bx,
         int ncx, int ldx,
         const float* __restrict__ biasr,
         float* __restrict__ c, float* __restrict__ hf,
         __half* __restrict__ hout) {
    extern __shared__ __align__(16) char smem[];
    cell_body<32>(smem, blockIdx.x * 32, blockIdx.y,
                  Ah, Bh, Ax, Bx, ncx, ldx, biasr, c, hf, hout);
}

// ---------------------------------------------------------------------------
// Merged encoder wavefront step: MT=64, grid (4,64)=256 CTAs, 2/SM resident.
// L1(t) on tiles y<32, L0(t+1) on tiles y>=32.
// ---------------------------------------------------------------------------
__global__ void __launch_bounds__(NTHREADS, 2)
enc_step(const __half* __restrict__ h1p, const __half* __restrict__ w1hh,
         const __half* __restrict__ y0t, const __half* __restrict__ w1ih,
         const float* __restrict__ br1, float* __restrict__ c1,
         float* __restrict__ h1f, __half* __restrict__ h1o,
         const __half* __restrict__ xn,
         const __half* __restrict__ w0, const __half* __restrict__ wx0,
         const float* __restrict__ br0, float* __restrict__ c0,
         float* __restrict__ h0f, __half* __restrict__ y0n) {
    extern __shared__ __align__(16) char smem[];
    const int m0 = blockIdx.x * 64;
    if (blockIdx.y < 32) {
        cell_body<64>(smem, m0, blockIdx.y,
                      h1p, w1hh, y0t, w1ih, 8, HID, br1, c1, h1f, h1o);
    } else {
        cell_body<64>(smem, m0, blockIdx.y - 32,
                      y0t, w0, xn, wx0, 1, XPW, br0, c0, h0f, y0n);
    }
}

// ---------------------------------------------------------------------------
// head: pred += h1 @ headW^T + headb ; write output[t]; build next decoder x
// ---------------------------------------------------------------------------
__global__ void head_kernel(const float* __restrict__ h1,
                            const float* __restrict__ headW,
                            const float* __restrict__ headb,
                            float* __restrict__ pred,
                            float* __restrict__ out_t,
                            const float* __restrict__ wf_next,
                            __half* __restrict__ xd) {
    int b = blockIdx.x;
    int w = threadIdx.x >> 5;
    int lane = threadIdx.x & 31;
    const float* hr = &h1[b * HID];
    const float* wr = &headW[w * HID];
    float s = 0.f;
    for (int k = lane; k < HID; k += 32) s += hr[k] * wr[k];
#pragma unroll
    for (int o = 16; o; o >>= 1) s += __shfl_down_sync(0xffffffffu, s, o);
    if (lane == 0) {
        float p = pred[b * VEG + w] + s + headb[w];
        pred[b * VEG + w] = p;
        out_t[b * (T_FUT * VEG) + w] = p;
        xd[b * XPW + w] = __float2half(p);
    }
    if (threadIdx.x < WEA && wf_next)
        xd[b * XPW + VEG + threadIdx.x] =
            __float2half(wf_next[b * (T_FUT * WEA) + threadIdx.x]);
}

// ---------------------------------------------------------------------------
// Host launcher (single stream — graph-capture safe)
// ---------------------------------------------------------------------------
extern "C" void kernel_launch(void* const* d_in, const int* in_sizes, int n_in,
                              void* d_out, int out_size) {
    const float* veg   = (const float*)d_in[0];
    const float* wh    = (const float*)d_in[1];
    const float* wf    = (const float*)d_in[2];
    const float* Wih0  = (const float*)d_in[3];
    const float* Whh0  = (const float*)d_in[4];
    const float* b0    = (const float*)d_in[5];
    const float* Wih1  = (const float*)d_in[6];
    const float* Whh1  = (const float*)d_in[7];
    const float* b1    = (const float*)d_in[8];
    const float* headW = (const float*)d_in[9];
    const float* headb = (const float*)d_in[10];
    float* out = (float*)d_out;

    __half *xp, *xd, *y0, *zb, *h1, *h0;
    __half *w0, *w1hh, *w1ih, *wx0;
    float *pred, *c0, *c1, *h1f, *h0f, *br0, *br1;
    cudaGetSymbolAddress((void**)&xp,    g_xp);
    cudaGetSymbolAddress((void**)&xd,    g_xd);
    cudaGetSymbolAddress((void**)&pred,  g_pred);
    cudaGetSymbolAddress((void**)&y0,    g_y0);
    cudaGetSymbolAddress((void**)&zb,    g_zb);
    cudaGetSymbolAddress((void**)&c0,    g_c0);
    cudaGetSymbolAddress((void**)&c1,    g_c1);
    cudaGetSymbolAddress((void**)&h1,    g_h1);
    cudaGetSymbolAddress((void**)&h0,    g_h0);
    cudaGetSymbolAddress((void**)&h1f,   g_h1f);
    cudaGetSymbolAddress((void**)&h0f,   g_h0f);
    cudaGetSymbolAddress((void**)&w0,    g_w0);
    cudaGetSymbolAddress((void**)&w1hh,  g_w1hh);
    cudaGetSymbolAddress((void**)&w1ih,  g_w1ih);
    cudaGetSymbolAddress((void**)&wx0,   g_wx0);
    cudaGetSymbolAddress((void**)&br0,   g_br0);
    cudaGetSymbolAddress((void**)&br1,   g_br1);

    cudaFuncSetAttribute(cell_mma, cudaFuncAttributeMaxDynamicSharedMemorySize,
                         SMEM_TOTAL_(32));
    cudaFuncSetAttribute(enc_step, cudaFuncAttributeMaxDynamicSharedMemorySize,
                         SMEM_TOTAL_(64));

    dim3 grid1(8, 32), grid2(4, 64), blk(NTHREADS);

    prep_kernel<<<T_HIST, NB>>>(veg, wh, wf, xp, xd, pred);
    wprep_kernel<<<GROW, 128>>>(Wih0, Whh0, b0, Wih1, Whh1, b1,
                                w0, w1hh, w1ih, wx0, br0, br1);
    zero_kernel<<<(HB + 255) / 256, 256>>>(c0, c1, zb);

    // L0(0) alone
    cell_mma<<<grid1, blk, SMEM_TOTAL_(32)>>>(
        zb, w0, xp, wx0, 1, XPW, br0, c0, h0f, y0);

    // merged wavefront: t = 0..148 computes L1(t) and L0(t+1) concurrently
    for (int t = 0; t < T_HIST - 1; t++) {
        const __half* h1p = (t == 0) ? zb : (h1 + ((t + 1) & 1) * HB);
        enc_step<<<grid2, blk, SMEM_TOTAL_(64)>>>(
            h1p, w1hh, y0 + (size_t)t * HB, w1ih,
            br1, c1, h1f, h1 + (t & 1) * HB,
            xp + (size_t)(t + 1) * NB * XPW,
            w0, wx0, br0, c0, h0f, y0 + (size_t)(t + 1) * HB);
    }
    // final L1(149): reads h1[148&1=0], writes h1[149&1=1]
    {
        int t = T_HIST - 1;
        cell_mma<<<grid1, blk, SMEM_TOTAL_(32)>>>(
            h1 + ((t + 1) & 1) * HB, w1hh,
            y0 + (size_t)t * HB, w1ih,
            8, HID, br1, c1, h1f, h1 + (t & 1) * HB);
    }

    // decoder (serial dependence); h1 phases: read (t+1)&1, write t&1
    for (int t = 0; t < T_FUT; t++) {
        const __half* hp = (t == 0) ? (y0 + (size_t)(T_HIST - 1) * HB)
                                    : (h0 + ((t + 1) & 1) * HB);
        cell_mma<<<grid1, blk, SMEM_TOTAL_(32)>>>(
            hp, w0, xd, wx0, 1, XPW, br0, c0, h0f, h0 + (t & 1) * HB);
        cell_mma<<<grid1, blk, SMEM_TOTAL_(32)>>>(
            h1 + ((t + 1) & 1) * HB, w1hh,
            h0 + (t & 1) * HB, w1ih,
            8, HID, br1, c1, h1f, h1 + (t & 1) * HB);
        const float* wfn = (t < T_FUT - 1) ? (wf + (t + 1) * WEA) : nullptr;
        head_kernel<<<NB, 128>>>(h1f, headW, headb, pred,
                                 out + t * VEG, wfn, xd);
    }
}

// round 15
// speedup vs baseline: 4.0902x; 1.0281x over previous
#include <cuda_runtime.h>
#include <cuda_fp16.h>
#include <cstdint>
#include <math.h>

// ---------------------------------------------------------------------------
// Problem constants
// ---------------------------------------------------------------------------
#define VEG 4
#define WEA 8
#define HID 512
#define NB  256
#define T_HIST 150
#define T_FUT  50
#define HB (NB * HID)
#define XPW 64            // padded x width (12 real + 52 zeros)
#define GROW 2048         // gate rows (4*HID)
#define NTHREADS 256      // 8 warps per CTA, occupancy 2
#define NCTA 256          // persistent grid (<= 296 resident slots at occ 2)

// ---------------------------------------------------------------------------
// Device scratch (static only) — pure fp16 activations and weights
// ---------------------------------------------------------------------------
__device__ __half g_xp[T_HIST * NB * XPW];
__device__ __half g_xd[NB * XPW];
__device__ float g_pred[NB * VEG];
__device__ __half g_y0[T_HIST * HB];     // layer0 outputs (h-chain)
__device__ __half g_zb[HB];              // fp16 zeros
__device__ float g_c0[HB];
__device__ float g_c1[HB];
__device__ __half g_h1[2 * HB];
__device__ __half g_h0[2 * HB];
__device__ float g_h1f[HB];
// reordered (row = u*4+g) fp16 weights
__device__ __half g_w0[GROW * HID];      // Whh0
__device__ __half g_w1hh[GROW * HID];    // Whh1
__device__ __half g_w1ih[GROW * HID];    // Wih1
__device__ __half g_wx0[GROW * XPW];     // Wih0 padded
__device__ float g_br0[GROW], g_br1[GROW];
// grid barrier state
__device__ unsigned g_cnt = 0;
__device__ unsigned g_gen = 0;

// ---------------------------------------------------------------------------
// Portable PTX helpers (sm_80+ only)
// ---------------------------------------------------------------------------
__device__ __forceinline__ uint32_t smem_u32(const void* p) {
    uint32_t a;
    asm("{ .reg .u64 t; cvta.to.shared.u64 t, %1; cvt.u32.u64 %0, t; }"
        : "=r"(a) : "l"(p));
    return a;
}
#define CP_ASYNC16(dst, src) \
    asm volatile("cp.async.cg.shared.global [%0], [%1], 16;" \
                 :: "r"(dst), "l"(src) : "memory")
#define CP_COMMIT() asm volatile("cp.async.commit_group;" ::: "memory")
#define CP_WAIT1()  asm volatile("cp.async.wait_group 1;" ::: "memory")
#define CP_WAIT0()  asm volatile("cp.async.wait_group 0;" ::: "memory")

#define LDM4(r, addr) \
    asm volatile("ldmatrix.sync.aligned.m8n8.x4.shared.b16 {%0,%1,%2,%3}, [%4];" \
                 : "=r"((r)[0]), "=r"((r)[1]), "=r"((r)[2]), "=r"((r)[3]) \
                 : "r"(addr))

#define MMA16816F(d, a, b0, b1) \
    asm volatile( \
        "mma.sync.aligned.m16n8k16.row.col.f32.f16.f16.f32 " \
        "{%0,%1,%2,%3}, {%4,%5,%6,%7}, {%8,%9}, {%0,%1,%2,%3};" \
        : "+f"((d)[0]), "+f"((d)[1]), "+f"((d)[2]), "+f"((d)[3]) \
        : "r"((a)[0]), "r"((a)[1]), "r"((a)[2]), "r"((a)[3]), \
          "r"(b0), "r"(b1))

// ---------------------------------------------------------------------------
// Grid barrier (all NCTA CTAs co-resident — guaranteed by occ 2, smem, grid)
// ---------------------------------------------------------------------------
__device__ __forceinline__ void grid_bar() {
    __syncthreads();
    if (threadIdx.x == 0) {
        __threadfence();
        unsigned gen = *(volatile unsigned*)&g_gen;
        if (atomicAdd(&g_cnt, 1u) == NCTA - 1) {
            g_cnt = 0;
            __threadfence();
            atomicAdd(&g_gen, 1u);
        } else {
            while (*(volatile unsigned*)&g_gen == gen) __nanosleep(64);
        }
        __threadfence();
    }
    __syncthreads();
}

// ---------------------------------------------------------------------------
// SMEM layout: A + B, 3 stages
// ---------------------------------------------------------------------------
#define SM_STRIDE 72                        // fp16 elems/row (144B, conflict-free)
#define ROW_B (SM_STRIDE * 2)               // 144 bytes
#define B_TILE_BYTES (64 * ROW_B)           // 9216
#define NSTAGE 3
#define CS_STRIDE 68                        // fp32 C tile row stride

#define A_TILE_BYTES_(MT) ((MT) * ROW_B)
#define STAGE_BYTES_(MT)  (A_TILE_BYTES_(MT) + B_TILE_BYTES)
#define OFF_BIAS_(MT)     (NSTAGE * STAGE_BYTES_(MT))
#define SMEM_TOTAL_(MT)   (OFF_BIAS_(MT) + 64 * 4 + 16)
// MT=64: stage 18432, total 55568 -> 2 CTAs/SM fits easily

// ---------------------------------------------------------------------------
// Math helpers
// ---------------------------------------------------------------------------
__device__ __forceinline__ float sigmoidf_(float x) { return 1.0f / (1.0f + __expf(-x)); }
__device__ __forceinline__ float tanhf_(float x)    { return 2.0f / (1.0f + __expf(-2.0f * x)) - 1.0f; }

// ---------------------------------------------------------------------------
// prep: smoothing + padded-x fp16 for encoder; decoder init at t=149
// ---------------------------------------------------------------------------
__global__ void prep_kernel(const float* __restrict__ veg,
                            const float* __restrict__ wh,
                            const float* __restrict__ wf,
                            __half* __restrict__ xp,
                            __half* __restrict__ xd,
                            float* __restrict__ pred) {
    int b = threadIdx.x;
    int t = blockIdx.x;
    const int base = (t * NB + b) * XPW;
    float vs[VEG];
#pragma unroll
    for (int v = 0; v < VEG; v++) {
        float val = veg[b * (T_HIST * VEG) + t * VEG + v];
        float s = 0.f;
#pragma unroll
        for (int dt = -2; dt <= 2; dt++) {
            int tt = t + dt;
            if (tt >= 0 && tt < T_HIST) {
                float u = veg[b * (T_HIST * VEG) + tt * VEG + v];
                if (!isnan(u)) s += u;
            }
        }
        float sm = s * 0.2f;
        float outv = isnan(val) ? sm : val;
        if (isnan(outv)) outv = 0.f;
        vs[v] = outv;
        xp[base + v] = __float2half(outv);
    }
#pragma unroll
    for (int k = 0; k < WEA; k++)
        xp[base + VEG + k] = __float2half(wh[b * (T_HIST * WEA) + t * WEA + k]);
    __half z = __float2half(0.f);
    for (int c = VEG + WEA; c < XPW; c++) xp[base + c] = z;

    if (t == T_HIST - 1) {
        int db = b * XPW;
#pragma unroll
        for (int v = 0; v < VEG; v++) {
            pred[b * VEG + v] = vs[v];
            xd[db + v] = __float2half(vs[v]);
        }
#pragma unroll
        for (int k = 0; k < WEA; k++)
            xd[db + VEG + k] = __float2half(wf[b * (T_FUT * WEA) + k]);
        for (int c = VEG + WEA; c < XPW; c++) xd[db + c] = z;
    }
}

// ---------------------------------------------------------------------------
// weight prep: reorder rows to u*4+g, fp16, pad Wih0 to 64 cols
// ---------------------------------------------------------------------------
__global__ void wprep_kernel(const float* __restrict__ Wih0, const float* __restrict__ Whh0,
                             const float* __restrict__ b0,   const float* __restrict__ Wih1,
                             const float* __restrict__ Whh1, const float* __restrict__ b1,
                             __half* w0, __half* w1hh, __half* w1ih, __half* wx0,
                             float* br0, float* br1) {
    int rn = blockIdx.x;                       // new row
    int orig = (rn & 3) * HID + (rn >> 2);     // g*512 + u
    for (int c = threadIdx.x; c < HID; c += blockDim.x) {
        w0[rn * HID + c]   = __float2half(Whh0[orig * HID + c]);
        w1hh[rn * HID + c] = __float2half(Whh1[orig * HID + c]);
        w1ih[rn * HID + c] = __float2half(Wih1[orig * HID + c]);
    }
    if (threadIdx.x < XPW) {
        int c = threadIdx.x;
        float v = (c < VEG + WEA) ? Wih0[orig * (VEG + WEA) + c] : 0.f;
        wx0[rn * XPW + c] = __float2half(v);
    }
    if (threadIdx.x == 0) { br0[rn] = b0[orig]; br1[rn] = b1[orig]; }
}

__global__ void zero_kernel(float* __restrict__ c0, float* __restrict__ c1,
                            __half* __restrict__ zb) {
    int i = blockIdx.x * blockDim.x + threadIdx.x;
    if (i < HB) { c0[i] = 0.f; c1[i] = 0.f; zb[i] = __float2half(0.f); }
}

// ---------------------------------------------------------------------------
// Cell body: one MT(batch)x64(gate) tile of a fused LSTM step on fp16 HMMA.
// All cross-CTA operand reads via cp.async.cg (L1-bypassing -> L2-coherent,
// safe across grid barriers). hf write optional.
// ---------------------------------------------------------------------------
template <int MT>
__device__ __forceinline__ void cell_body(
    char* smem, int m0, int tileY,
    const __half* __restrict__ Ah, const __half* __restrict__ Bh,   // h, Whh
    const __half* __restrict__ Ax, const __half* __restrict__ Bx,   // x, Wx
    int ncx, int ldx,
    const float* __restrict__ biasr,
    float* __restrict__ c, float* __restrict__ hf,
    __half* __restrict__ hout) {

    constexpr int A_TILE = A_TILE_BYTES_(MT);
    constexpr int STAGE  = STAGE_BYTES_(MT);
    constexpr int OFF_A  = 0;
    constexpr int OFF_B  = A_TILE;
    constexpr int OFF_BIAS = OFF_BIAS_(MT);
    constexpr int WM = MT / 32;           // M warp-slices (1 or 2)
    constexpr int KS = 8 / (WM * 2);      // K-groups (4 or 2)
    constexpr int KITER = 4 / KS;         // kk slices per warp per chunk
    constexpr int CSLAB = MT * CS_STRIDE; // floats per K-group C slab
    static_assert(WM * 2 * KS == 8, "warp layout");

    const uint32_t sbase = smem_u32(smem);
    const int tid = threadIdx.x;
    const int warp = tid >> 5;
    const int lane = tid & 31;
    const int n0 = tileY * 64;            // reordered weight row base
    const int u0 = tileY * 16;            // unit base
    const int ks = warp % KS;
    const int rem = warp / KS;
    const int wn = rem & 1;               // 0..1 (32-col slices)
    const int wm = rem >> 1;              // 0..WM-1 (32-row slices)

    if (tid < 64)
        *reinterpret_cast<float*>(smem + OFF_BIAS + tid * 4) = biasr[n0 + tid];

    float cf[2][4][4];
#pragma unroll
    for (int mi = 0; mi < 2; mi++)
#pragma unroll
        for (int nj = 0; nj < 4; nj++)
#pragma unroll
            for (int r = 0; r < 4; r++) cf[mi][nj][r] = 0.f;

    const int NC = 8 + ncx;

    auto prefetch = [&](int ch) {
        const __half *aP, *bP;
        int lda, k0;
        if (ch < 8) { aP = Ah; bP = Bh; lda = HID; k0 = ch * 64; }
        else        { aP = Ax; bP = Bx; lda = ldx; k0 = (ch - 8) * 64; }
        const uint32_t st = sbase + (ch % NSTAGE) * STAGE;
#pragma unroll
        for (int i = 0; i < (MT * 8) / NTHREADS; i++) {
            int idx = tid + i * NTHREADS;
            int r = idx >> 3, q = idx & 7;
            uint32_t off = r * ROW_B + q * 16;
            long ao = (long)(m0 + r) * lda + k0 + q * 8;
            CP_ASYNC16(st + OFF_A + off, aP + ao);
        }
#pragma unroll
        for (int i = 0; i < 512 / NTHREADS; i++) {
            int idx = tid + i * NTHREADS;
            int r = idx >> 3, q = idx & 7;
            uint32_t off = r * ROW_B + q * 16;
            long bo = (long)(n0 + r) * lda + k0 + q * 8;
            CP_ASYNC16(st + OFF_B + off, bP + bo);
        }
    };

    prefetch(0); CP_COMMIT();
    prefetch(1); CP_COMMIT();

    for (int ch = 0; ch < NC; ch++) {
        if (ch + 1 < NC) CP_WAIT1(); else CP_WAIT0();
        __syncthreads();                    // publishes chunk ch
        if (ch + 2 < NC) { prefetch(ch + 2); CP_COMMIT(); }

        const uint32_t base = sbase + (ch % NSTAGE) * STAGE;
#pragma unroll
        for (int ki = 0; ki < KITER; ki++) {
            const int kk = (ks * KITER + ki) * 16;
            uint32_t ah[2][4], bh[4][2];
#pragma unroll
            for (int mi = 0; mi < 2; mi++) {
                uint32_t roff =
                    (uint32_t)((wm * 32 + mi * 16 + (lane & 15)) * ROW_B +
                               (kk + (lane >> 4) * 8) * 2);
                LDM4(ah[mi], base + OFF_A + roff);
            }
#pragma unroll
            for (int p = 0; p < 2; p++) {
                uint32_t roff =
                    (uint32_t)((wn * 32 + p * 16 + (lane & 15)) * ROW_B +
                               (kk + (lane >> 4) * 8) * 2);
                uint32_t rb[4];
                LDM4(rb, base + OFF_B + roff);
                bh[p * 2 + 0][0] = rb[0]; bh[p * 2 + 0][1] = rb[2];
                bh[p * 2 + 1][0] = rb[1]; bh[p * 2 + 1][1] = rb[3];
            }
#pragma unroll
            for (int mi = 0; mi < 2; mi++)
#pragma unroll
                for (int nj = 0; nj < 4; nj++)
                    MMA16816F(cf[mi][nj], ah[mi], bh[nj][0], bh[nj][1]);
        }
    }
    __syncthreads();   // all ldmatrix reads done before Cs overwrites stage 0

    // ---- epilogue: per-K-group C slabs (single barrier) ----
    float* Cs = reinterpret_cast<float*>(smem);   // KS slabs of MT x CS_STRIDE
    {
        float* Cg = Cs + ks * CSLAB;
#pragma unroll
        for (int mi = 0; mi < 2; mi++)
#pragma unroll
            for (int nj = 0; nj < 4; nj++) {
                int r = wm * 32 + mi * 16 + (lane >> 2);
                int col = wn * 32 + nj * 8 + (lane & 3) * 2;
                Cg[r * CS_STRIDE + col]           = cf[mi][nj][0];
                Cg[r * CS_STRIDE + col + 1]       = cf[mi][nj][1];
                Cg[(r + 8) * CS_STRIDE + col]     = cf[mi][nj][2];
                Cg[(r + 8) * CS_STRIDE + col + 1] = cf[mi][nj][3];
            }
    }
    __syncthreads();

    const float* Bs = reinterpret_cast<const float*>(smem + OFF_BIAS);
#pragma unroll
    for (int k = 0; k < (MT * 16) / NTHREADS; k++) {
        int id = tid + k * NTHREADS;
        int u = id & 15, bb = id >> 4;        // bb 0..MT-1
        float4 g4 = *reinterpret_cast<const float4*>(&Cs[bb * CS_STRIDE + u * 4]);
#pragma unroll
        for (int g = 1; g < KS; g++) {
            float4 p4 = *reinterpret_cast<const float4*>(
                &Cs[g * CSLAB + bb * CS_STRIDE + u * 4]);
            g4.x += p4.x; g4.y += p4.y; g4.z += p4.z; g4.w += p4.w;
        }
        float gi = sigmoidf_(g4.x + Bs[u * 4 + 0]);
        float gf = sigmoidf_(g4.y + Bs[u * 4 + 1]);
        float gg = tanhf_   (g4.z + Bs[u * 4 + 2]);
        float go = sigmoidf_(g4.w + Bs[u * 4 + 3]);
        int gidx = (m0 + bb) * HID + u0 + u;
        float cn = gf * c[gidx] + gi * gg;
        c[gidx] = cn;
        float hv = go * tanhf_(cn);
        if (hf) hf[gidx] = hv;
        hout[gidx] = __float2half(hv);
    }
}

// ---------------------------------------------------------------------------
// THE persistent kernel: whole network after prep. 256 CTAs, occ 2 (all
// co-resident), software grid barriers between dependent phases.
// ---------------------------------------------------------------------------
__global__ void __launch_bounds__(NTHREADS, 2)
lstm_persist(const __half* __restrict__ xp, __half* __restrict__ xd,
             const __half* __restrict__ zb,
             const __half* __restrict__ w0,   const __half* __restrict__ wx0,
             const float* __restrict__ br0,  float* __restrict__ c0,
             const __half* __restrict__ w1hh, const __half* __restrict__ w1ih,
             const float* __restrict__ br1,  float* __restrict__ c1,
             __half* __restrict__ y0, __half* __restrict__ h1,
             __half* __restrict__ h0, float* __restrict__ h1f,
             const float* __restrict__ headW, const float* __restrict__ headb,
             const float* __restrict__ wf,
             float* __restrict__ pred, float* __restrict__ out) {
    extern __shared__ __align__(16) char smem[];
    const int bid = blockIdx.x;

    // ===== encoder: L1 on CTAs 0..127 (4x32 tiles, MT=64), L0 on 128..255 ====
    {
        const bool isL1 = bid < 128;
        const int rem = isL1 ? bid : bid - 128;
        const int m0 = (rem >> 5) * 64;
        const int yt = rem & 31;

        if (!isL1)   // L0(0): A = zeros, X = xp[0]
            cell_body<64>(smem, m0, yt, zb, w0, xp, wx0,
                          1, XPW, br0, c0, nullptr, y0);
        grid_bar();

        for (int t = 0; t < T_HIST; t++) {      // t = 0..149
            if (isL1) {
                const __half* h1p = (t == 0) ? zb : (h1 + ((t + 1) & 1) * HB);
                cell_body<64>(smem, m0, yt, h1p, w1hh,
                              y0 + (size_t)t * HB, w1ih,
                              8, HID, br1, c1, nullptr, h1 + (t & 1) * HB);
            } else if (t < T_HIST - 1) {
                cell_body<64>(smem, m0, yt, y0 + (size_t)t * HB, w0,
                              xp + (size_t)(t + 1) * NB * XPW, wx0,
                              1, XPW, br0, c0, nullptr,
                              y0 + (size_t)(t + 1) * HB);
            }
            grid_bar();
        }
    }

    // ===== decoder: all 256 CTAs (8x32 tiles, MT=32); 3 phases per step =====
    {
        const int m0 = (bid >> 5) * 32;
        const int yt = bid & 31;
        for (int t = 0; t < T_FUT; t++) {
            // L0(t): A = h0 prev (or y0[149]), X = xd
            const __half* hp = (t == 0) ? (y0 + (size_t)(T_HIST - 1) * HB)
                                        : (h0 + ((t + 1) & 1) * HB);
            cell_body<32>(smem, m0, yt, hp, w0, xd, wx0,
                          1, XPW, br0, c0, nullptr, h0 + (t & 1) * HB);
            grid_bar();
            // L1(t): A = h1 prev (enc ended at index 1; read (t+1)&1, write t&1)
            cell_body<32>(smem, m0, yt, h1 + ((t + 1) & 1) * HB, w1hh,
                          h0 + (t & 1) * HB, w1ih,
                          8, HID, br1, c1, h1f, h1 + (t & 1) * HB);
            grid_bar();
            // head: CTA bid handles batch b = bid
            {
                const int b = bid;
                if (threadIdx.x < 128) {
                    int w = threadIdx.x >> 5;
                    int lane = threadIdx.x & 31;
                    const float* hr = h1f + b * HID;
                    const float* wr = headW + w * HID;
                    float s = 0.f;
                    for (int k = lane; k < HID; k += 32)
                        s += __ldcg(hr + k) * wr[k];   // L1-bypass: cross-CTA
#pragma unroll
                    for (int o = 16; o; o >>= 1)
                        s += __shfl_down_sync(0xffffffffu, s, o);
                    if (lane == 0) {
                        float p = pred[b * VEG + w] + s + headb[w];
                        pred[b * VEG + w] = p;
                        out[b * (T_FUT * VEG) + t * VEG + w] = p;
                        xd[b * XPW + w] = __float2half(p);
                    }
                    if (threadIdx.x < WEA && t + 1 < T_FUT)
                        xd[b * XPW + VEG + threadIdx.x] = __float2half(
                            wf[b * (T_FUT * WEA) + (t + 1) * WEA + threadIdx.x]);
                }
            }
            grid_bar();
        }
    }
}

// ---------------------------------------------------------------------------
// Host launcher (single stream — graph-capture safe; ONE main kernel)
// ---------------------------------------------------------------------------
extern "C" void kernel_launch(void* const* d_in, const int* in_sizes, int n_in,
                              void* d_out, int out_size) {
    const float* veg   = (const float*)d_in[0];
    const float* wh    = (const float*)d_in[1];
    const float* wf    = (const float*)d_in[2];
    const float* Wih0  = (const float*)d_in[3];
    const float* Whh0  = (const float*)d_in[4];
    const float* b0    = (const float*)d_in[5];
    const float* Wih1  = (const float*)d_in[6];
    const float* Whh1  = (const float*)d_in[7];
    const float* b1    = (const float*)d_in[8];
    const float* headW = (const float*)d_in[9];
    const float* headb = (const float*)d_in[10];
    float* out = (float*)d_out;

    __half *xp, *xd, *y0, *zb, *h1, *h0;
    __half *w0, *w1hh, *w1ih, *wx0;
    float *pred, *c0, *c1, *h1f, *br0, *br1;
    cudaGetSymbolAddress((void**)&xp,    g_xp);
    cudaGetSymbolAddress((void**)&xd,    g_xd);
    cudaGetSymbolAddress((void**)&pred,  g_pred);
    cudaGetSymbolAddress((void**)&y0,    g_y0);
    cudaGetSymbolAddress((void**)&zb,    g_zb);
    cudaGetSymbolAddress((void**)&c0,    g_c0);
    cudaGetSymbolAddress((void**)&c1,    g_c1);
    cudaGetSymbolAddress((void**)&h1,    g_h1);
    cudaGetSymbolAddress((void**)&h0,    g_h0);
    cudaGetSymbolAddress((void**)&h1f,   g_h1f);
    cudaGetSymbolAddress((void**)&w0,    g_w0);
    cudaGetSymbolAddress((void**)&w1hh,  g_w1hh);
    cudaGetSymbolAddress((void**)&w1ih,  g_w1ih);
    cudaGetSymbolAddress((void**)&wx0,   g_wx0);
    cudaGetSymbolAddress((void**)&br0,   g_br0);
    cudaGetSymbolAddress((void**)&br1,   g_br1);

    cudaFuncSetAttribute(lstm_persist,
                         cudaFuncAttributeMaxDynamicSharedMemorySize,
                         SMEM_TOTAL_(64));

    prep_kernel<<<T_HIST, NB>>>(veg, wh, wf, xp, xd, pred);
    wprep_kernel<<<GROW, 128>>>(Wih0, Whh0, b0, Wih1, Whh1, b1,
                                w0, w1hh, w1ih, wx0, br0, br1);
    zero_kernel<<<(HB + 255) / 256, 256>>>(c0, c1, zb);

    lstm_persist<<<NCTA, NTHREADS, SMEM_TOTAL_(64)>>>(
        xp, xd, zb,
        w0, wx0, br0, c0,
        w1hh, w1ih, br1, c1,
        y0, h1, h0, h1f,
        headW, headb, wf, pred, out);
}